// round 7
// baseline (speedup 1.0000x reference)
#include <cuda_runtime.h>
#include <cuda_bf16.h>
#include <math_constants.h>
#include <cstdint>

// Problem constants
#define B_ 4
#define N_ 2048
#define C_ 1024
#define H_ 16
#define D_ 64
#define SCALE_ 0.125f   // 1/sqrt(64)

// ---------------------------------------------------------------------------
// Scratch (device globals: allocation-free)
// ---------------------------------------------------------------------------
__device__ __nv_bfloat16 g_qhi[B_ * H_ * N_ * D_];   // q pre-scaled by 0.125
__device__ __nv_bfloat16 g_qlo[B_ * H_ * N_ * D_];
__device__ __nv_bfloat16 g_khi[B_ * H_ * N_ * D_];
__device__ __nv_bfloat16 g_klo[B_ * H_ * N_ * D_];
__device__ __nv_bfloat16 g_vhi[B_ * H_ * N_ * D_];
__device__ __nv_bfloat16 g_vlo[B_ * H_ * N_ * D_];

__device__ __nv_bfloat16 g_xhi[B_ * N_ * C_];        // X split [8192][1024]
__device__ __nv_bfloat16 g_xlo[B_ * N_ * C_];
__device__ __nv_bfloat16 g_ahi[B_ * N_ * C_];        // attention out split
__device__ __nv_bfloat16 g_alo[B_ * N_ * C_];
__device__ __nv_bfloat16 g_wqkv_hi[3 * C_ * C_];     // W_qkv^T split [3072][1024]
__device__ __nv_bfloat16 g_wqkv_lo[3 * C_ * C_];
__device__ __nv_bfloat16 g_wp_hi[C_ * C_];           // W_proj^T split [1024][1024]
__device__ __nv_bfloat16 g_wp_lo[C_ * C_];

// ---------------------------------------------------------------------------
// PTX helpers (sm_103 base ISA)
// ---------------------------------------------------------------------------
__device__ __forceinline__ uint32_t smem_to_u32(const void* p) {
    uint32_t a;
    asm("{ .reg .u64 t; cvta.to.shared.u64 t, %1; cvt.u32.u64 %0, t; }"
        : "=r"(a) : "l"(p));
    return a;
}

#define CP_ASYNC16(saddr, gptr) \
    asm volatile("cp.async.cg.shared.global [%0], [%1], 16;" \
                 :: "r"(saddr), "l"(gptr) : "memory")
#define CP_COMMIT() asm volatile("cp.async.commit_group;" ::: "memory")
#define CP_WAIT1()  asm volatile("cp.async.wait_group 1;" ::: "memory")
#define CP_WAIT0()  asm volatile("cp.async.wait_group 0;" ::: "memory")

#define LDSM_X4(r0, r1, r2, r3, addr) \
    asm volatile("ldmatrix.sync.aligned.m8n8.x4.shared.b16 {%0,%1,%2,%3}, [%4];" \
                 : "=r"(r0), "=r"(r1), "=r"(r2), "=r"(r3) : "r"(addr))
#define LDSM_X4_T(r0, r1, r2, r3, addr) \
    asm volatile("ldmatrix.sync.aligned.m8n8.x4.trans.shared.b16 {%0,%1,%2,%3}, [%4];" \
                 : "=r"(r0), "=r"(r1), "=r"(r2), "=r"(r3) : "r"(addr))

#define MMA16816(d, a, b0, b1) \
    asm volatile("mma.sync.aligned.m16n8k16.row.col.f32.bf16.bf16.f32 " \
                 "{%0,%1,%2,%3}, {%4,%5,%6,%7}, {%8,%9}, {%0,%1,%2,%3};" \
                 : "+f"((d)[0]), "+f"((d)[1]), "+f"((d)[2]), "+f"((d)[3]) \
                 : "r"((a)[0]), "r"((a)[1]), "r"((a)[2]), "r"((a)[3]), \
                   "r"(b0), "r"(b1))

// split f0,f1 into bf16 hi/lo packed pairs
__device__ __forceinline__ void pack_split(float f0, float f1,
                                           uint32_t& hi, uint32_t& lo) {
    __nv_bfloat16 h0 = __float2bfloat16(f0), h1 = __float2bfloat16(f1);
    __nv_bfloat162 Hh; Hh.x = h0; Hh.y = h1;
    __nv_bfloat162 Ll;
    Ll.x = __float2bfloat16(f0 - __bfloat162float(h0));
    Ll.y = __float2bfloat16(f1 - __bfloat162float(h1));
    hi = *(uint32_t*)&Hh;
    lo = *(uint32_t*)&Ll;
}
__device__ __forceinline__ void split_store2(__nv_bfloat16* hi, __nv_bfloat16* lo,
                                             size_t idx, float f0, float f1) {
    uint32_t uh, ul;
    pack_split(f0, f1, uh, ul);
    *(uint32_t*)(hi + idx) = uh;
    *(uint32_t*)(lo + idx) = ul;
}

// ---------------------------------------------------------------------------
// fp32 x -> bf16 hi/lo split
// ---------------------------------------------------------------------------
__global__ __launch_bounds__(256) void split_kernel(const float* __restrict__ in, int n4)
{
    int i = blockIdx.x * 256 + threadIdx.x;
    if (i >= n4) return;
    float4 v = ((const float4*)in)[i];
    union U { __nv_bfloat16 b[4]; uint2 u; } Hh, Ll;
    float vv[4] = {v.x, v.y, v.z, v.w};
#pragma unroll
    for (int j = 0; j < 4; j++) {
        __nv_bfloat16 h = __float2bfloat16(vv[j]);
        Hh.b[j] = h;
        Ll.b[j] = __float2bfloat16(vv[j] - __bfloat162float(h));
    }
    ((uint2*)g_xhi)[i] = Hh.u;
    ((uint2*)g_xlo)[i] = Ll.u;
}

// ---------------------------------------------------------------------------
// fp32 W[K=1024][Ncols] -> transposed bf16 hi/lo [Ncols][1024]
// ---------------------------------------------------------------------------
template<int DST>
__global__ __launch_bounds__(256) void splitT_kernel(const float* __restrict__ in, int Ccols)
{
    __nv_bfloat16* hi = (DST == 0) ? g_wqkv_hi : g_wp_hi;
    __nv_bfloat16* lo = (DST == 0) ? g_wqkv_lo : g_wp_lo;
    __shared__ float t[32][33];
    int tx = threadIdx.x & 31;
    int ty = threadIdx.x >> 5;
    int n_base = blockIdx.x * 32;
    int k_base = blockIdx.y * 32;
#pragma unroll
    for (int i = 0; i < 4; i++) {
        int k = k_base + ty + i * 8;
        t[ty + i * 8][tx] = in[(size_t)k * Ccols + n_base + tx];
    }
    __syncthreads();
#pragma unroll
    for (int i = 0; i < 4; i++) {
        int nn = n_base + ty + i * 8;
        int k = k_base + tx;
        float v = t[tx][ty + i * 8];
        __nv_bfloat16 h = __float2bfloat16(v);
        hi[(size_t)nn * C_ + k] = h;
        lo[(size_t)nn * C_ + k] = __float2bfloat16(v - __bfloat162float(h));
    }
}

// ---------------------------------------------------------------------------
// HMMA bf16-split GEMM, 128x128 tile, BK=32, double-buffered cp.async.
// Term-major MMA ordering: same-accumulator reuse distance = 16.
// MODE 0: X @ Wqkv^T -> bf16 hi/lo q(scaled)/k/v     MODE 1: att @ Wp^T -> out
// ---------------------------------------------------------------------------
#define GBK 32
#define LDA 40
#define MAT_ELEMS (128 * LDA)
#define STAGE_ELEMS (4 * MAT_ELEMS)
#define SMEM_GEMM (2 * STAGE_ELEMS * 2)

template<int MODE>
__global__ __launch_bounds__(256) void mma_gemm_kernel(
    const float* __restrict__ bias, float* __restrict__ outp)
{
    const __nv_bfloat16* Ahi = (MODE == 0) ? g_xhi : g_ahi;
    const __nv_bfloat16* Alo = (MODE == 0) ? g_xlo : g_alo;
    const __nv_bfloat16* Bhi = (MODE == 0) ? g_wqkv_hi : g_wp_hi;
    const __nv_bfloat16* Blo = (MODE == 0) ? g_wqkv_lo : g_wp_lo;

    extern __shared__ __nv_bfloat16 sm[];
    const uint32_t sbase = smem_to_u32(sm);
    const int tid = threadIdx.x;
    const int wid = tid >> 5, lane = tid & 31;
    const int warp_m = wid & 3;
    const int warp_n = wid >> 2;
    const int m0 = blockIdx.y * 128;
    const int n0 = blockIdx.x * 128;

    float acc[2][8][4];
#pragma unroll
    for (int a = 0; a < 2; a++)
#pragma unroll
        for (int b = 0; b < 8; b++)
#pragma unroll
            for (int c = 0; c < 4; c++) acc[a][b][c] = 0.f;

    const int row = tid >> 2;
    const int un = tid & 3;

    auto load_stage = [&](int s) {
        const int buf = s & 1;
        const int k0 = s * GBK;
        const uint32_t sb = sbase + (uint32_t)buf * STAGE_ELEMS * 2;
        const __nv_bfloat16* srcs[4] = {Ahi, Alo, Bhi, Blo};
#pragma unroll
        for (int mat = 0; mat < 4; mat++) {
            const int rbase = (mat < 2) ? m0 : n0;
            const __nv_bfloat16* src = srcs[mat];
#pragma unroll
            for (int i = 0; i < 2; i++) {
                int r = row + i * 64;
                uint32_t so = sb + (uint32_t)(mat * MAT_ELEMS + r * LDA + un * 8) * 2;
                CP_ASYNC16(so, src + (size_t)(rbase + r) * C_ + k0 + un * 8);
            }
        }
        CP_COMMIT();
    };

    constexpr int NS = C_ / GBK;
    load_stage(0);

    for (int s = 0; s < NS; s++) {
        if (s + 1 < NS) { load_stage(s + 1); CP_WAIT1(); }
        else            { CP_WAIT0(); }
        __syncthreads();

        const uint32_t sb = sbase + (uint32_t)(s & 1) * STAGE_ELEMS * 2;
        const int lrow = lane & 15;
        const int lk = (lane >> 4) * 8;

#pragma unroll
        for (int kk = 0; kk < GBK; kk += 16) {
            uint32_t ah[2][4], al[2][4], bh[4][4], bl[4][4];
#pragma unroll
            for (int mt = 0; mt < 2; mt++) {
                uint32_t off = (uint32_t)((warp_m * 32 + mt * 16 + lrow) * LDA + kk + lk) * 2;
                LDSM_X4(ah[mt][0], ah[mt][1], ah[mt][2], ah[mt][3], sb + off);
                LDSM_X4(al[mt][0], al[mt][1], al[mt][2], al[mt][3],
                        sb + (uint32_t)MAT_ELEMS * 2 + off);
            }
#pragma unroll
            for (int np = 0; np < 4; np++) {
                uint32_t off = (uint32_t)((warp_n * 64 + np * 16 + lrow) * LDA + kk + lk) * 2;
                LDSM_X4(bh[np][0], bh[np][1], bh[np][2], bh[np][3],
                        sb + (uint32_t)(2 * MAT_ELEMS) * 2 + off);
                LDSM_X4(bl[np][0], bl[np][1], bl[np][2], bl[np][3],
                        sb + (uint32_t)(3 * MAT_ELEMS) * 2 + off);
            }
            // term-major: 16 distinct accumulators between same-acc MMAs
#pragma unroll
            for (int mt = 0; mt < 2; mt++)
#pragma unroll
                for (int np = 0; np < 4; np++)
#pragma unroll
                    for (int sel = 0; sel < 2; sel++)
                        MMA16816(acc[mt][np * 2 + sel], ah[mt], bh[np][sel], bh[np][2 + sel]);
#pragma unroll
            for (int mt = 0; mt < 2; mt++)
#pragma unroll
                for (int np = 0; np < 4; np++)
#pragma unroll
                    for (int sel = 0; sel < 2; sel++)
                        MMA16816(acc[mt][np * 2 + sel], ah[mt], bl[np][sel], bl[np][2 + sel]);
#pragma unroll
            for (int mt = 0; mt < 2; mt++)
#pragma unroll
                for (int np = 0; np < 4; np++)
#pragma unroll
                    for (int sel = 0; sel < 2; sel++)
                        MMA16816(acc[mt][np * 2 + sel], al[mt], bh[np][sel], bh[np][2 + sel]);
        }
        __syncthreads();
    }

    // ---- epilogue ----
#pragma unroll
    for (int mt = 0; mt < 2; mt++) {
#pragma unroll
        for (int nt = 0; nt < 8; nt++) {
            int r = m0 + warp_m * 32 + mt * 16 + (lane >> 2);
            int c = n0 + warp_n * 64 + nt * 8 + (lane & 3) * 2;
            float b0 = bias[c], b1 = bias[c + 1];
            float s00 = acc[mt][nt][0] + b0, s01 = acc[mt][nt][1] + b1;
            float s10 = acc[mt][nt][2] + b0, s11 = acc[mt][nt][3] + b1;
            if (MODE == 0) {
                int bb = r >> 11, tok = r & 2047;
                int which = c >> 10, ch = c & 1023, h = ch >> 6, d0 = ch & 63;
                __nv_bfloat16* dhi = (which == 0) ? g_qhi : (which == 1) ? g_khi : g_vhi;
                __nv_bfloat16* dlo = (which == 0) ? g_qlo : (which == 1) ? g_klo : g_vlo;
                if (which == 0) { s00 *= SCALE_; s01 *= SCALE_; s10 *= SCALE_; s11 *= SCALE_; }
                size_t base = (((size_t)bb * H_ + h) * N_ + tok) * D_ + d0;
                split_store2(dhi, dlo, base, s00, s01);
                split_store2(dhi, dlo, base + 8 * D_, s10, s11);
            } else {
                *(float2*)(outp + (size_t)r * C_ + c) = make_float2(s00, s01);
                *(float2*)(outp + (size_t)(r + 8) * C_ + c) = make_float2(s10, s11);
            }
        }
    }
}

// ---------------------------------------------------------------------------
// MMA flash attention.  CTA = (b,h) x 128 queries.  8 warps x 16 rows.
// Key chunks of 64, double-buffered cp.async (Khi,Klo,Vhi,Vlo).
// Term-major MMA ordering, same-acc distance 4.
// ---------------------------------------------------------------------------
#define ALDK 72                            // padded row (elems)
#define AMAT (64 * ALDK)                   // 4608 elems
#define AMAT_B (AMAT * 2)                  // 9216 bytes
#define ASTAGE_B (4 * AMAT_B)              // 36864 bytes
#define SMEM_ATTN (2 * ASTAGE_B)           // 73728 bytes

__global__ __launch_bounds__(256) void attn_mma_kernel()
{
    extern __shared__ __nv_bfloat16 smx[];
    const uint32_t sb = smem_to_u32(smx);
    const int tid = threadIdx.x;
    const int wid = tid >> 5, lane = tid & 31;
    const int bh = blockIdx.x;
    const int r0t = blockIdx.y * 128;
    const size_t qoff = (size_t)bh * N_ * D_;

    // ---- stage Q tile (128x64 hi/lo) through smem, read fragments ----
#pragma unroll
    for (int i = 0; i < 4; i++) {
        int s = tid + 256 * i;
        int r = s >> 3, c8 = s & 7;
        uint32_t so = (uint32_t)(r * ALDK + c8 * 8) * 2;
        *(uint4*)((char*)smx + so) =
            *(const uint4*)(g_qhi + qoff + (size_t)(r0t + r) * D_ + c8 * 8);
        *(uint4*)((char*)smx + (uint32_t)(128 * ALDK) * 2 + so) =
            *(const uint4*)(g_qlo + qoff + (size_t)(r0t + r) * D_ + c8 * 8);
    }
    __syncthreads();

    uint32_t qh[4][4], ql[4][4];
    {
        const int rb = wid * 16 + (lane & 15);
        const int cb = (lane >> 4) * 8;
#pragma unroll
        for (int kk = 0; kk < 4; kk++) {
            uint32_t addr = sb + (uint32_t)(rb * ALDK + kk * 16 + cb) * 2;
            LDSM_X4(qh[kk][0], qh[kk][1], qh[kk][2], qh[kk][3], addr);
            LDSM_X4(ql[kk][0], ql[kk][1], ql[kk][2], ql[kk][3],
                    addr + (uint32_t)(128 * ALDK) * 2);
        }
    }
    __syncthreads();

    float accO[8][4];
#pragma unroll
    for (int t = 0; t < 8; t++)
#pragma unroll
        for (int j = 0; j < 4; j++) accO[t][j] = 0.f;
    float mrow[2] = {-CUDART_INF_F, -CUDART_INF_F};
    float lrow[2] = {0.f, 0.f};

    auto load_stage = [&](int c) {
        const uint32_t base = sb + (uint32_t)(c & 1) * ASTAGE_B;
        const int k0 = c * 64;
        const __nv_bfloat16* mats[4] = {g_khi, g_klo, g_vhi, g_vlo};
#pragma unroll
        for (int i = 0; i < 8; i++) {
            int mat = i >> 1;
            int s = tid + 256 * (i & 1);
            int r = s >> 3, c8 = s & 7;
            uint32_t so = base + (uint32_t)mat * AMAT_B + (uint32_t)(r * ALDK + c8 * 8) * 2;
            CP_ASYNC16(so, mats[mat] + qoff + (size_t)(k0 + r) * D_ + c8 * 8);
        }
        CP_COMMIT();
    };

    load_stage(0);
    const int lr = lane & 15;
    const int lc = (lane >> 4) * 8;

    for (int c = 0; c < N_ / 64; c++) {
        if (c + 1 < N_ / 64) { load_stage(c + 1); CP_WAIT1(); }
        else                 { CP_WAIT0(); }
        __syncthreads();

        const uint32_t base = sb + (uint32_t)(c & 1) * ASTAGE_B;
        const uint32_t Kh = base, Kl = base + AMAT_B;
        const uint32_t Vh = base + 2 * AMAT_B, Vl = base + 3 * AMAT_B;

        // ---- S = Q K^T (3-term, term-major, acc distance 4) ----
        float accS[8][4];
#pragma unroll
        for (int t = 0; t < 8; t++)
#pragma unroll
            for (int j = 0; j < 4; j++) accS[t][j] = 0.f;

#pragma unroll
        for (int kk = 0; kk < 4; kk++) {
#pragma unroll
            for (int hp = 0; hp < 2; hp++) {
                const int ng0 = hp * 2, ng1 = hp * 2 + 1;
                uint32_t ha[4], la[4], hb[4], lb[4];
                uint32_t offa = (uint32_t)((ng0 * 16 + lr) * ALDK + kk * 16 + lc) * 2;
                uint32_t offb = (uint32_t)((ng1 * 16 + lr) * ALDK + kk * 16 + lc) * 2;
                LDSM_X4(ha[0], ha[1], ha[2], ha[3], Kh + offa);
                LDSM_X4(la[0], la[1], la[2], la[3], Kl + offa);
                LDSM_X4(hb[0], hb[1], hb[2], hb[3], Kh + offb);
                LDSM_X4(lb[0], lb[1], lb[2], lb[3], Kl + offb);
                MMA16816(accS[2 * ng0],     qh[kk], ha[0], ha[2]);
                MMA16816(accS[2 * ng0 + 1], qh[kk], ha[1], ha[3]);
                MMA16816(accS[2 * ng1],     qh[kk], hb[0], hb[2]);
                MMA16816(accS[2 * ng1 + 1], qh[kk], hb[1], hb[3]);
                MMA16816(accS[2 * ng0],     qh[kk], la[0], la[2]);
                MMA16816(accS[2 * ng0 + 1], qh[kk], la[1], la[3]);
                MMA16816(accS[2 * ng1],     qh[kk], lb[0], lb[2]);
                MMA16816(accS[2 * ng1 + 1], qh[kk], lb[1], lb[3]);
                MMA16816(accS[2 * ng0],     ql[kk], ha[0], ha[2]);
                MMA16816(accS[2 * ng0 + 1], ql[kk], ha[1], ha[3]);
                MMA16816(accS[2 * ng1],     ql[kk], hb[0], hb[2]);
                MMA16816(accS[2 * ng1 + 1], ql[kk], hb[1], hb[3]);
            }
        }

        // ---- online softmax (q already scaled by 0.125) ----
#pragma unroll
        for (int p = 0; p < 2; p++) {
            float vm = accS[0][2 * p];
#pragma unroll
            for (int t = 0; t < 8; t++) {
                vm = fmaxf(vm, accS[t][2 * p]);
                vm = fmaxf(vm, accS[t][2 * p + 1]);
            }
            vm = fmaxf(vm, __shfl_xor_sync(0xffffffffu, vm, 1));
            vm = fmaxf(vm, __shfl_xor_sync(0xffffffffu, vm, 2));
            float mn = fmaxf(mrow[p], vm);
            float alpha = __expf(mrow[p] - mn);
            float sum = 0.f;
#pragma unroll
            for (int t = 0; t < 8; t++) {
                float e0 = __expf(accS[t][2 * p]     - mn);
                float e1 = __expf(accS[t][2 * p + 1] - mn);
                accS[t][2 * p] = e0; accS[t][2 * p + 1] = e1;
                sum += e0 + e1;
            }
            sum += __shfl_xor_sync(0xffffffffu, sum, 1);
            sum += __shfl_xor_sync(0xffffffffu, sum, 2);
            lrow[p] = lrow[p] * alpha + sum;
            mrow[p] = mn;
#pragma unroll
            for (int t = 0; t < 8; t++) {
                accO[t][2 * p]     *= alpha;
                accO[t][2 * p + 1] *= alpha;
            }
        }

        // ---- O += P V (3-term, term-major, acc distance 4) ----
#pragma unroll
        for (int kk = 0; kk < 4; kk++) {
            uint32_t ph[4], pl[4];
            pack_split(accS[2 * kk][0],     accS[2 * kk][1],     ph[0], pl[0]);
            pack_split(accS[2 * kk][2],     accS[2 * kk][3],     ph[1], pl[1]);
            pack_split(accS[2 * kk + 1][0], accS[2 * kk + 1][1], ph[2], pl[2]);
            pack_split(accS[2 * kk + 1][2], accS[2 * kk + 1][3], ph[3], pl[3]);
#pragma unroll
            for (int dp = 0; dp < 2; dp++) {
                const int dg0 = dp * 2, dg1 = dp * 2 + 1;
                uint32_t va[4], wa[4], vb[4], wb[4];
                uint32_t offa = (uint32_t)((kk * 16 + lr) * ALDK + dg0 * 16 + lc) * 2;
                uint32_t offb = (uint32_t)((kk * 16 + lr) * ALDK + dg1 * 16 + lc) * 2;
                LDSM_X4_T(va[0], va[1], va[2], va[3], Vh + offa);
                LDSM_X4_T(wa[0], wa[1], wa[2], wa[3], Vl + offa);
                LDSM_X4_T(vb[0], vb[1], vb[2], vb[3], Vh + offb);
                LDSM_X4_T(wb[0], wb[1], wb[2], wb[3], Vl + offb);
                MMA16816(accO[2 * dg0],     ph, va[0], va[1]);
                MMA16816(accO[2 * dg0 + 1], ph, va[2], va[3]);
                MMA16816(accO[2 * dg1],     ph, vb[0], vb[1]);
                MMA16816(accO[2 * dg1 + 1], ph, vb[2], vb[3]);
                MMA16816(accO[2 * dg0],     pl, va[0], va[1]);
                MMA16816(accO[2 * dg0 + 1], pl, va[2], va[3]);
                MMA16816(accO[2 * dg1],     pl, vb[0], vb[1]);
                MMA16816(accO[2 * dg1 + 1], pl, vb[2], vb[3]);
                MMA16816(accO[2 * dg0],     ph, wa[0], wa[1]);
                MMA16816(accO[2 * dg0 + 1], ph, wa[2], wa[3]);
                MMA16816(accO[2 * dg1],     ph, wb[0], wb[1]);
                MMA16816(accO[2 * dg1 + 1], ph, wb[2], wb[3]);
            }
        }
        __syncthreads();
    }

    // ---- epilogue: normalize, split to bf16 hi/lo in [B][N][C] ----
    const int b = bh >> 4;
    const int h = bh & 15;
    const float inv0 = 1.0f / lrow[0];
    const float inv1 = 1.0f / lrow[1];
    const int row0 = r0t + wid * 16 + (lane >> 2);
#pragma unroll
    for (int t = 0; t < 8; t++) {
        int col = h * 64 + t * 8 + (lane & 3) * 2;
        split_store2(g_ahi, g_alo, ((size_t)b * N_ + row0) * C_ + col,
                     accO[t][0] * inv0, accO[t][1] * inv0);
        split_store2(g_ahi, g_alo, ((size_t)b * N_ + row0 + 8) * C_ + col,
                     accO[t][2] * inv1, accO[t][3] * inv1);
    }
}

// ---------------------------------------------------------------------------
extern "C" void kernel_launch(void* const* d_in, const int* in_sizes, int n_in,
                              void* d_out, int out_size)
{
    const float* x      = (const float*)d_in[0];
    const float* w_qkv  = (const float*)d_in[1];
    const float* b_qkv  = (const float*)d_in[2];
    const float* w_proj = (const float*)d_in[3];
    const float* b_proj = (const float*)d_in[4];
    float* out = (float*)d_out;

    cudaFuncSetAttribute(mma_gemm_kernel<0>,
                         cudaFuncAttributeMaxDynamicSharedMemorySize, SMEM_GEMM);
    cudaFuncSetAttribute(mma_gemm_kernel<1>,
                         cudaFuncAttributeMaxDynamicSharedMemorySize, SMEM_GEMM);
    cudaFuncSetAttribute(attn_mma_kernel,
                         cudaFuncAttributeMaxDynamicSharedMemorySize, SMEM_ATTN);

    // 1. Split conversions
    {
        int n4 = B_ * N_ * C_ / 4;
        split_kernel<<<(n4 + 255) / 256, 256>>>(x, n4);
        dim3 g1(3 * C_ / 32, C_ / 32);
        splitT_kernel<0><<<g1, 256>>>(w_qkv, 3 * C_);
        dim3 g2(C_ / 32, C_ / 32);
        splitT_kernel<1><<<g2, 256>>>(w_proj, C_);
    }

    // 2. QKV GEMM -> bf16 hi/lo q(scaled)/k/v
    {
        dim3 grid(3 * C_ / 128, (B_ * N_) / 128);
        mma_gemm_kernel<0><<<grid, 256, SMEM_GEMM>>>(b_qkv, nullptr);
    }

    // 3. MMA flash attention -> g_ahi/g_alo
    {
        dim3 grid(B_ * H_, N_ / 128);
        attn_mma_kernel<<<grid, 256, SMEM_ATTN>>>();
    }

    // 4. Projection GEMM -> out
    {
        dim3 grid(C_ / 128, (B_ * N_) / 128);
        mma_gemm_kernel<1><<<grid, 256, SMEM_GEMM>>>(b_proj, out);
    }
}

// round 8
// speedup vs baseline: 1.0760x; 1.0760x over previous
#include <cuda_runtime.h>
#include <cuda_bf16.h>
#include <math_constants.h>
#include <cstdint>

// Problem constants
#define B_ 4
#define N_ 2048
#define C_ 1024
#define H_ 16
#define D_ 64
#define SCALE_ 0.125f   // 1/sqrt(64)

// ---------------------------------------------------------------------------
// Scratch (device globals: allocation-free)
// ---------------------------------------------------------------------------
__device__ __nv_bfloat16 g_qhi[B_ * H_ * N_ * D_];   // q pre-scaled by 0.125
__device__ __nv_bfloat16 g_qlo[B_ * H_ * N_ * D_];
__device__ __nv_bfloat16 g_khi[B_ * H_ * N_ * D_];
__device__ __nv_bfloat16 g_klo[B_ * H_ * N_ * D_];
__device__ __nv_bfloat16 g_vhi[B_ * H_ * N_ * D_];
__device__ __nv_bfloat16 g_vlo[B_ * H_ * N_ * D_];

__device__ __nv_bfloat16 g_xhi[B_ * N_ * C_];        // X split [8192][1024]
__device__ __nv_bfloat16 g_xlo[B_ * N_ * C_];
__device__ __nv_bfloat16 g_ahi[B_ * N_ * C_];        // attention out split
__device__ __nv_bfloat16 g_alo[B_ * N_ * C_];
__device__ __nv_bfloat16 g_wqkv_hi[3 * C_ * C_];     // W_qkv^T split [3072][1024]
__device__ __nv_bfloat16 g_wqkv_lo[3 * C_ * C_];
__device__ __nv_bfloat16 g_wp_hi[C_ * C_];           // W_proj^T split [1024][1024]
__device__ __nv_bfloat16 g_wp_lo[C_ * C_];

// ---------------------------------------------------------------------------
// PTX helpers (sm_103 base ISA)
// ---------------------------------------------------------------------------
__device__ __forceinline__ uint32_t smem_to_u32(const void* p) {
    uint32_t a;
    asm("{ .reg .u64 t; cvta.to.shared.u64 t, %1; cvt.u32.u64 %0, t; }"
        : "=r"(a) : "l"(p));
    return a;
}

#define CP_ASYNC16(saddr, gptr) \
    asm volatile("cp.async.cg.shared.global [%0], [%1], 16;" \
                 :: "r"(saddr), "l"(gptr) : "memory")
#define CP_COMMIT() asm volatile("cp.async.commit_group;" ::: "memory")
#define CP_WAIT1()  asm volatile("cp.async.wait_group 1;" ::: "memory")
#define CP_WAIT0()  asm volatile("cp.async.wait_group 0;" ::: "memory")

#define LDSM_X4(r0, r1, r2, r3, addr) \
    asm volatile("ldmatrix.sync.aligned.m8n8.x4.shared.b16 {%0,%1,%2,%3}, [%4];" \
                 : "=r"(r0), "=r"(r1), "=r"(r2), "=r"(r3) : "r"(addr))
#define LDSM_X4_T(r0, r1, r2, r3, addr) \
    asm volatile("ldmatrix.sync.aligned.m8n8.x4.trans.shared.b16 {%0,%1,%2,%3}, [%4];" \
                 : "=r"(r0), "=r"(r1), "=r"(r2), "=r"(r3) : "r"(addr))

#define MMA16816(d, a, b0, b1) \
    asm volatile("mma.sync.aligned.m16n8k16.row.col.f32.bf16.bf16.f32 " \
                 "{%0,%1,%2,%3}, {%4,%5,%6,%7}, {%8,%9}, {%0,%1,%2,%3};" \
                 : "+f"((d)[0]), "+f"((d)[1]), "+f"((d)[2]), "+f"((d)[3]) \
                 : "r"((a)[0]), "r"((a)[1]), "r"((a)[2]), "r"((a)[3]), \
                   "r"(b0), "r"(b1))

// split f0,f1 into bf16 hi/lo packed pairs
__device__ __forceinline__ void pack_split(float f0, float f1,
                                           uint32_t& hi, uint32_t& lo) {
    __nv_bfloat16 h0 = __float2bfloat16(f0), h1 = __float2bfloat16(f1);
    __nv_bfloat162 Hh; Hh.x = h0; Hh.y = h1;
    __nv_bfloat162 Ll;
    Ll.x = __float2bfloat16(f0 - __bfloat162float(h0));
    Ll.y = __float2bfloat16(f1 - __bfloat162float(h1));
    hi = *(uint32_t*)&Hh;
    lo = *(uint32_t*)&Ll;
}
__device__ __forceinline__ void split_store2(__nv_bfloat16* hi, __nv_bfloat16* lo,
                                             size_t idx, float f0, float f1) {
    uint32_t uh, ul;
    pack_split(f0, f1, uh, ul);
    *(uint32_t*)(hi + idx) = uh;
    *(uint32_t*)(lo + idx) = ul;
}

// ---------------------------------------------------------------------------
// fp32 x -> bf16 hi/lo split
// ---------------------------------------------------------------------------
__global__ __launch_bounds__(256) void split_kernel(const float* __restrict__ in, int n4)
{
    int i = blockIdx.x * 256 + threadIdx.x;
    if (i >= n4) return;
    float4 v = ((const float4*)in)[i];
    union U { __nv_bfloat16 b[4]; uint2 u; } Hh, Ll;
    float vv[4] = {v.x, v.y, v.z, v.w};
#pragma unroll
    for (int j = 0; j < 4; j++) {
        __nv_bfloat16 h = __float2bfloat16(vv[j]);
        Hh.b[j] = h;
        Ll.b[j] = __float2bfloat16(vv[j] - __bfloat162float(h));
    }
    ((uint2*)g_xhi)[i] = Hh.u;
    ((uint2*)g_xlo)[i] = Ll.u;
}

// ---------------------------------------------------------------------------
// fp32 W[K=1024][Ncols] -> transposed bf16 hi/lo [Ncols][1024]
// ---------------------------------------------------------------------------
template<int DST>
__global__ __launch_bounds__(256) void splitT_kernel(const float* __restrict__ in, int Ccols)
{
    __nv_bfloat16* hi = (DST == 0) ? g_wqkv_hi : g_wp_hi;
    __nv_bfloat16* lo = (DST == 0) ? g_wqkv_lo : g_wp_lo;
    __shared__ float t[32][33];
    int tx = threadIdx.x & 31;
    int ty = threadIdx.x >> 5;
    int n_base = blockIdx.x * 32;
    int k_base = blockIdx.y * 32;
#pragma unroll
    for (int i = 0; i < 4; i++) {
        int k = k_base + ty + i * 8;
        t[ty + i * 8][tx] = in[(size_t)k * Ccols + n_base + tx];
    }
    __syncthreads();
#pragma unroll
    for (int i = 0; i < 4; i++) {
        int nn = n_base + ty + i * 8;
        int k = k_base + tx;
        float v = t[tx][ty + i * 8];
        __nv_bfloat16 h = __float2bfloat16(v);
        hi[(size_t)nn * C_ + k] = h;
        lo[(size_t)nn * C_ + k] = __float2bfloat16(v - __bfloat162float(h));
    }
}

// ---------------------------------------------------------------------------
// HMMA bf16-split GEMM.  CTA tile 128x64, 4 warps (warp tile 32x64), BK=32,
// double-buffered cp.async, 3 CTAs/SM.  Tail-wave-friendly grid.
// MODE 0: X @ Wqkv^T -> bf16 hi/lo q(scaled)/k/v     MODE 1: att @ Wp^T -> out
// ---------------------------------------------------------------------------
#define GBK 32
#define LDA 40
#define MAT_A (128 * LDA)                    // 5120 elems
#define MAT_B (64 * LDA)                     // 2560 elems
#define STG_ELEMS (2 * MAT_A + 2 * MAT_B)    // 15360 elems
#define SMEM_GEMM (2 * STG_ELEMS * 2)        // 61440 bytes

template<int MODE>
__global__ __launch_bounds__(128, 3) void mma_gemm_kernel(
    const float* __restrict__ bias, float* __restrict__ outp)
{
    const __nv_bfloat16* Ahi = (MODE == 0) ? g_xhi : g_ahi;
    const __nv_bfloat16* Alo = (MODE == 0) ? g_xlo : g_alo;
    const __nv_bfloat16* Bhi = (MODE == 0) ? g_wqkv_hi : g_wp_hi;
    const __nv_bfloat16* Blo = (MODE == 0) ? g_wqkv_lo : g_wp_lo;

    extern __shared__ __nv_bfloat16 sm[];
    const uint32_t sbase = smem_to_u32(sm);
    const int tid = threadIdx.x;
    const int wid = tid >> 5, lane = tid & 31;
    const int m0 = blockIdx.y * 128;
    const int n0 = blockIdx.x * 64;

    float acc[2][8][4];
#pragma unroll
    for (int a = 0; a < 2; a++)
#pragma unroll
        for (int b = 0; b < 8; b++)
#pragma unroll
            for (int c = 0; c < 4; c++) acc[a][b][c] = 0.f;

    auto load_stage = [&](int s) {
        const int buf = s & 1;
        const int k0 = s * GBK;
        const uint32_t sb = sbase + (uint32_t)buf * STG_ELEMS * 2;
        // A hi/lo: 512 chunks each, 4 per thread
#pragma unroll
        for (int i = 0; i < 4; i++) {
            int cch = tid + i * 128;           // 0..511
            int r = cch >> 2, kc = cch & 3;
            uint32_t so = (uint32_t)(r * LDA + kc * 8) * 2;
            size_t g = (size_t)(m0 + r) * C_ + k0 + kc * 8;
            CP_ASYNC16(sb + so, Ahi + g);
            CP_ASYNC16(sb + (uint32_t)MAT_A * 2 + so, Alo + g);
        }
        // B hi/lo: 256 chunks each, 2 per thread
#pragma unroll
        for (int i = 0; i < 2; i++) {
            int cch = tid + i * 128;           // 0..255
            int r = cch >> 2, kc = cch & 3;
            uint32_t so = (uint32_t)(r * LDA + kc * 8) * 2;
            size_t g = (size_t)(n0 + r) * C_ + k0 + kc * 8;
            CP_ASYNC16(sb + (uint32_t)(2 * MAT_A) * 2 + so, Bhi + g);
            CP_ASYNC16(sb + (uint32_t)(2 * MAT_A + MAT_B) * 2 + so, Blo + g);
        }
        CP_COMMIT();
    };

    constexpr int NS = C_ / GBK;   // 32
    load_stage(0);

    const int lrow = lane & 15;
    const int lk = (lane >> 4) * 8;

    for (int s = 0; s < NS; s++) {
        if (s + 1 < NS) { load_stage(s + 1); CP_WAIT1(); }
        else            { CP_WAIT0(); }
        __syncthreads();

        const uint32_t sb = sbase + (uint32_t)(s & 1) * STG_ELEMS * 2;

#pragma unroll
        for (int kk = 0; kk < GBK; kk += 16) {
            uint32_t ah[2][4], al[2][4], bh[4][4], bl[4][4];
#pragma unroll
            for (int mt = 0; mt < 2; mt++) {
                uint32_t off = (uint32_t)((wid * 32 + mt * 16 + lrow) * LDA + kk + lk) * 2;
                LDSM_X4(ah[mt][0], ah[mt][1], ah[mt][2], ah[mt][3], sb + off);
                LDSM_X4(al[mt][0], al[mt][1], al[mt][2], al[mt][3],
                        sb + (uint32_t)MAT_A * 2 + off);
            }
#pragma unroll
            for (int np = 0; np < 4; np++) {
                uint32_t off = (uint32_t)((np * 16 + lrow) * LDA + kk + lk) * 2;
                LDSM_X4(bh[np][0], bh[np][1], bh[np][2], bh[np][3],
                        sb + (uint32_t)(2 * MAT_A) * 2 + off);
                LDSM_X4(bl[np][0], bl[np][1], bl[np][2], bl[np][3],
                        sb + (uint32_t)(2 * MAT_A + MAT_B) * 2 + off);
            }
            // term-major
#pragma unroll
            for (int mt = 0; mt < 2; mt++)
#pragma unroll
                for (int np = 0; np < 4; np++)
#pragma unroll
                    for (int sel = 0; sel < 2; sel++)
                        MMA16816(acc[mt][np * 2 + sel], ah[mt], bh[np][sel], bh[np][2 + sel]);
#pragma unroll
            for (int mt = 0; mt < 2; mt++)
#pragma unroll
                for (int np = 0; np < 4; np++)
#pragma unroll
                    for (int sel = 0; sel < 2; sel++)
                        MMA16816(acc[mt][np * 2 + sel], ah[mt], bl[np][sel], bl[np][2 + sel]);
#pragma unroll
            for (int mt = 0; mt < 2; mt++)
#pragma unroll
                for (int np = 0; np < 4; np++)
#pragma unroll
                    for (int sel = 0; sel < 2; sel++)
                        MMA16816(acc[mt][np * 2 + sel], al[mt], bh[np][sel], bh[np][2 + sel]);
        }
        __syncthreads();
    }

    // ---- epilogue ----
#pragma unroll
    for (int mt = 0; mt < 2; mt++) {
#pragma unroll
        for (int nt = 0; nt < 8; nt++) {
            int r = m0 + wid * 32 + mt * 16 + (lane >> 2);
            int c = n0 + nt * 8 + (lane & 3) * 2;
            float b0 = bias[c], b1 = bias[c + 1];
            float s00 = acc[mt][nt][0] + b0, s01 = acc[mt][nt][1] + b1;
            float s10 = acc[mt][nt][2] + b0, s11 = acc[mt][nt][3] + b1;
            if (MODE == 0) {
                int bb = r >> 11, tok = r & 2047;
                int which = c >> 10, ch = c & 1023, h = ch >> 6, d0 = ch & 63;
                __nv_bfloat16* dhi = (which == 0) ? g_qhi : (which == 1) ? g_khi : g_vhi;
                __nv_bfloat16* dlo = (which == 0) ? g_qlo : (which == 1) ? g_klo : g_vlo;
                if (which == 0) { s00 *= SCALE_; s01 *= SCALE_; s10 *= SCALE_; s11 *= SCALE_; }
                size_t base = (((size_t)bb * H_ + h) * N_ + tok) * D_ + d0;
                split_store2(dhi, dlo, base, s00, s01);
                split_store2(dhi, dlo, base + 8 * D_, s10, s11);
            } else {
                *(float2*)(outp + (size_t)r * C_ + c) = make_float2(s00, s01);
                *(float2*)(outp + (size_t)(r + 8) * C_ + c) = make_float2(s10, s11);
            }
        }
    }
}

// ---------------------------------------------------------------------------
// MMA flash attention.  CTA = (b,h) x 64 queries, 4 warps x 16 rows.
// Key chunks of 64, double-buffered cp.async (Khi,Klo,Vhi,Vlo), 3 CTAs/SM.
// 3-term bf16 split for S and PV.
// ---------------------------------------------------------------------------
#define ALDK 72                            // padded row (elems)
#define AMAT (64 * ALDK)                   // 4608 elems
#define AMAT_B (AMAT * 2)                  // 9216 bytes
#define ASTAGE_B (4 * AMAT_B)              // 36864 bytes
#define SMEM_ATTN (2 * ASTAGE_B)           // 73728 bytes

__global__ __launch_bounds__(128, 3) void attn_mma_kernel()
{
    extern __shared__ __nv_bfloat16 smx[];
    const uint32_t sb = smem_to_u32(smx);
    const int tid = threadIdx.x;
    const int wid = tid >> 5, lane = tid & 31;
    const int bh = blockIdx.x;
    const int r0t = blockIdx.y * 64;
    const size_t qoff = (size_t)bh * N_ * D_;

    // ---- stage Q tile (64x64 hi/lo) through smem, read fragments ----
#pragma unroll
    for (int i = 0; i < 4; i++) {
        int s = tid + 128 * i;             // 0..511
        int r = s >> 3, c8 = s & 7;
        uint32_t so = (uint32_t)(r * ALDK + c8 * 8) * 2;
        *(uint4*)((char*)smx + so) =
            *(const uint4*)(g_qhi + qoff + (size_t)(r0t + r) * D_ + c8 * 8);
        *(uint4*)((char*)smx + (uint32_t)(64 * ALDK) * 2 + so) =
            *(const uint4*)(g_qlo + qoff + (size_t)(r0t + r) * D_ + c8 * 8);
    }
    __syncthreads();

    uint32_t qh[4][4], ql[4][4];
    {
        const int rb = wid * 16 + (lane & 15);
        const int cb = (lane >> 4) * 8;
#pragma unroll
        for (int kk = 0; kk < 4; kk++) {
            uint32_t addr = sb + (uint32_t)(rb * ALDK + kk * 16 + cb) * 2;
            LDSM_X4(qh[kk][0], qh[kk][1], qh[kk][2], qh[kk][3], addr);
            LDSM_X4(ql[kk][0], ql[kk][1], ql[kk][2], ql[kk][3],
                    addr + (uint32_t)(64 * ALDK) * 2);
        }
    }
    __syncthreads();

    float accO[8][4];
#pragma unroll
    for (int t = 0; t < 8; t++)
#pragma unroll
        for (int j = 0; j < 4; j++) accO[t][j] = 0.f;
    float mrow[2] = {-CUDART_INF_F, -CUDART_INF_F};
    float lrow[2] = {0.f, 0.f};

    auto load_stage = [&](int c) {
        const uint32_t base = sb + (uint32_t)(c & 1) * ASTAGE_B;
        const int k0 = c * 64;
        const __nv_bfloat16* mats[4] = {g_khi, g_klo, g_vhi, g_vlo};
#pragma unroll
        for (int mat = 0; mat < 4; mat++) {
#pragma unroll
            for (int i = 0; i < 4; i++) {
                int s = tid + 128 * i;     // 0..511
                int r = s >> 3, c8 = s & 7;
                uint32_t so = base + (uint32_t)mat * AMAT_B
                            + (uint32_t)(r * ALDK + c8 * 8) * 2;
                CP_ASYNC16(so, mats[mat] + qoff + (size_t)(k0 + r) * D_ + c8 * 8);
            }
        }
        CP_COMMIT();
    };

    load_stage(0);
    const int lr = lane & 15;
    const int lc = (lane >> 4) * 8;

    for (int c = 0; c < N_ / 64; c++) {
        if (c + 1 < N_ / 64) { load_stage(c + 1); CP_WAIT1(); }
        else                 { CP_WAIT0(); }
        __syncthreads();

        const uint32_t base = sb + (uint32_t)(c & 1) * ASTAGE_B;
        const uint32_t Kh = base, Kl = base + AMAT_B;
        const uint32_t Vh = base + 2 * AMAT_B, Vl = base + 3 * AMAT_B;

        // ---- S = Q K^T (3-term, term-major) ----
        float accS[8][4];
#pragma unroll
        for (int t = 0; t < 8; t++)
#pragma unroll
            for (int j = 0; j < 4; j++) accS[t][j] = 0.f;

#pragma unroll
        for (int kk = 0; kk < 4; kk++) {
#pragma unroll
            for (int hp = 0; hp < 2; hp++) {
                const int ng0 = hp * 2, ng1 = hp * 2 + 1;
                uint32_t ha[4], la[4], hb[4], lb[4];
                uint32_t offa = (uint32_t)((ng0 * 16 + lr) * ALDK + kk * 16 + lc) * 2;
                uint32_t offb = (uint32_t)((ng1 * 16 + lr) * ALDK + kk * 16 + lc) * 2;
                LDSM_X4(ha[0], ha[1], ha[2], ha[3], Kh + offa);
                LDSM_X4(la[0], la[1], la[2], la[3], Kl + offa);
                LDSM_X4(hb[0], hb[1], hb[2], hb[3], Kh + offb);
                LDSM_X4(lb[0], lb[1], lb[2], lb[3], Kl + offb);
                MMA16816(accS[2 * ng0],     qh[kk], ha[0], ha[2]);
                MMA16816(accS[2 * ng0 + 1], qh[kk], ha[1], ha[3]);
                MMA16816(accS[2 * ng1],     qh[kk], hb[0], hb[2]);
                MMA16816(accS[2 * ng1 + 1], qh[kk], hb[1], hb[3]);
                MMA16816(accS[2 * ng0],     qh[kk], la[0], la[2]);
                MMA16816(accS[2 * ng0 + 1], qh[kk], la[1], la[3]);
                MMA16816(accS[2 * ng1],     qh[kk], lb[0], lb[2]);
                MMA16816(accS[2 * ng1 + 1], qh[kk], lb[1], lb[3]);
                MMA16816(accS[2 * ng0],     ql[kk], ha[0], ha[2]);
                MMA16816(accS[2 * ng0 + 1], ql[kk], ha[1], ha[3]);
                MMA16816(accS[2 * ng1],     ql[kk], hb[0], hb[2]);
                MMA16816(accS[2 * ng1 + 1], ql[kk], hb[1], hb[3]);
            }
        }

        // ---- online softmax (q already scaled by 0.125) ----
#pragma unroll
        for (int p = 0; p < 2; p++) {
            float vm = accS[0][2 * p];
#pragma unroll
            for (int t = 0; t < 8; t++) {
                vm = fmaxf(vm, accS[t][2 * p]);
                vm = fmaxf(vm, accS[t][2 * p + 1]);
            }
            vm = fmaxf(vm, __shfl_xor_sync(0xffffffffu, vm, 1));
            vm = fmaxf(vm, __shfl_xor_sync(0xffffffffu, vm, 2));
            float mn = fmaxf(mrow[p], vm);
            float alpha = __expf(mrow[p] - mn);
            float sum = 0.f;
#pragma unroll
            for (int t = 0; t < 8; t++) {
                float e0 = __expf(accS[t][2 * p]     - mn);
                float e1 = __expf(accS[t][2 * p + 1] - mn);
                accS[t][2 * p] = e0; accS[t][2 * p + 1] = e1;
                sum += e0 + e1;
            }
            sum += __shfl_xor_sync(0xffffffffu, sum, 1);
            sum += __shfl_xor_sync(0xffffffffu, sum, 2);
            lrow[p] = lrow[p] * alpha + sum;
            mrow[p] = mn;
#pragma unroll
            for (int t = 0; t < 8; t++) {
                accO[t][2 * p]     *= alpha;
                accO[t][2 * p + 1] *= alpha;
            }
        }

        // ---- O += P V (3-term, term-major) ----
#pragma unroll
        for (int kk = 0; kk < 4; kk++) {
            uint32_t ph[4], pl[4];
            pack_split(accS[2 * kk][0],     accS[2 * kk][1],     ph[0], pl[0]);
            pack_split(accS[2 * kk][2],     accS[2 * kk][3],     ph[1], pl[1]);
            pack_split(accS[2 * kk + 1][0], accS[2 * kk + 1][1], ph[2], pl[2]);
            pack_split(accS[2 * kk + 1][2], accS[2 * kk + 1][3], ph[3], pl[3]);
#pragma unroll
            for (int dp = 0; dp < 2; dp++) {
                const int dg0 = dp * 2, dg1 = dp * 2 + 1;
                uint32_t va[4], wa[4], vb[4], wb[4];
                uint32_t offa = (uint32_t)((kk * 16 + lr) * ALDK + dg0 * 16 + lc) * 2;
                uint32_t offb = (uint32_t)((kk * 16 + lr) * ALDK + dg1 * 16 + lc) * 2;
                LDSM_X4_T(va[0], va[1], va[2], va[3], Vh + offa);
                LDSM_X4_T(wa[0], wa[1], wa[2], wa[3], Vl + offa);
                LDSM_X4_T(vb[0], vb[1], vb[2], vb[3], Vh + offb);
                LDSM_X4_T(wb[0], wb[1], wb[2], wb[3], Vl + offb);
                MMA16816(accO[2 * dg0],     ph, va[0], va[1]);
                MMA16816(accO[2 * dg0 + 1], ph, va[2], va[3]);
                MMA16816(accO[2 * dg1],     ph, vb[0], vb[1]);
                MMA16816(accO[2 * dg1 + 1], ph, vb[2], vb[3]);
                MMA16816(accO[2 * dg0],     pl, va[0], va[1]);
                MMA16816(accO[2 * dg0 + 1], pl, va[2], va[3]);
                MMA16816(accO[2 * dg1],     pl, vb[0], vb[1]);
                MMA16816(accO[2 * dg1 + 1], pl, vb[2], vb[3]);
                MMA16816(accO[2 * dg0],     ph, wa[0], wa[1]);
                MMA16816(accO[2 * dg0 + 1], ph, wa[2], wa[3]);
                MMA16816(accO[2 * dg1],     ph, wb[0], wb[1]);
                MMA16816(accO[2 * dg1 + 1], ph, wb[2], wb[3]);
            }
        }
        __syncthreads();
    }

    // ---- epilogue: normalize, split to bf16 hi/lo in [B][N][C] ----
    const int b = bh >> 4;
    const int h = bh & 15;
    const float inv0 = 1.0f / lrow[0];
    const float inv1 = 1.0f / lrow[1];
    const int row0 = r0t + wid * 16 + (lane >> 2);
#pragma unroll
    for (int t = 0; t < 8; t++) {
        int col = h * 64 + t * 8 + (lane & 3) * 2;
        split_store2(g_ahi, g_alo, ((size_t)b * N_ + row0) * C_ + col,
                     accO[t][0] * inv0, accO[t][1] * inv0);
        split_store2(g_ahi, g_alo, ((size_t)b * N_ + row0 + 8) * C_ + col,
                     accO[t][2] * inv1, accO[t][3] * inv1);
    }
}

// ---------------------------------------------------------------------------
extern "C" void kernel_launch(void* const* d_in, const int* in_sizes, int n_in,
                              void* d_out, int out_size)
{
    const float* x      = (const float*)d_in[0];
    const float* w_qkv  = (const float*)d_in[1];
    const float* b_qkv  = (const float*)d_in[2];
    const float* w_proj = (const float*)d_in[3];
    const float* b_proj = (const float*)d_in[4];
    float* out = (float*)d_out;

    cudaFuncSetAttribute(mma_gemm_kernel<0>,
                         cudaFuncAttributeMaxDynamicSharedMemorySize, SMEM_GEMM);
    cudaFuncSetAttribute(mma_gemm_kernel<1>,
                         cudaFuncAttributeMaxDynamicSharedMemorySize, SMEM_GEMM);
    cudaFuncSetAttribute(attn_mma_kernel,
                         cudaFuncAttributeMaxDynamicSharedMemorySize, SMEM_ATTN);

    // 1. Split conversions
    {
        int n4 = B_ * N_ * C_ / 4;
        split_kernel<<<(n4 + 255) / 256, 256>>>(x, n4);
        dim3 g1(3 * C_ / 32, C_ / 32);
        splitT_kernel<0><<<g1, 256>>>(w_qkv, 3 * C_);
        dim3 g2(C_ / 32, C_ / 32);
        splitT_kernel<1><<<g2, 256>>>(w_proj, C_);
    }

    // 2. QKV GEMM -> bf16 hi/lo q(scaled)/k/v
    {
        dim3 grid(3 * C_ / 64, (B_ * N_) / 128);   // (48, 64)
        mma_gemm_kernel<0><<<grid, 128, SMEM_GEMM>>>(b_qkv, nullptr);
    }

    // 3. MMA flash attention -> g_ahi/g_alo
    {
        dim3 grid(B_ * H_, N_ / 64);               // (64, 32)
        attn_mma_kernel<<<grid, 128, SMEM_ATTN>>>();
    }

    // 4. Projection GEMM -> out
    {
        dim3 grid(C_ / 64, (B_ * N_) / 128);       // (16, 64)
        mma_gemm_kernel<1><<<grid, 128, SMEM_GEMM>>>(b_proj, out);
    }
}

// round 9
// speedup vs baseline: 1.3755x; 1.2783x over previous
#include <cuda_runtime.h>
#include <cuda_fp16.h>
#include <math_constants.h>
#include <cstdint>

// Problem constants
#define B_ 4
#define N_ 2048
#define C_ 1024
#define H_ 16
#define D_ 64
#define SCALE_ 0.125f   // 1/sqrt(64)

// ---------------------------------------------------------------------------
// Scratch (device globals: allocation-free).  fp16 hi/lo scheme:
//   GEMM A-side (activations): hi+lo.  GEMM B-side (weights): hi only.
//   Attention: Q hi only, K hi+lo, V hi+lo, att-out hi+lo.
// ---------------------------------------------------------------------------
__device__ __half g_qh[B_ * H_ * N_ * D_];    // q pre-scaled by 0.125
__device__ __half g_kh[B_ * H_ * N_ * D_];
__device__ __half g_kl[B_ * H_ * N_ * D_];
__device__ __half g_vh[B_ * H_ * N_ * D_];
__device__ __half g_vl[B_ * H_ * N_ * D_];

__device__ __half g_xh[B_ * N_ * C_];         // X split [8192][1024]
__device__ __half g_xl[B_ * N_ * C_];
__device__ __half g_ah[B_ * N_ * C_];         // attention out split
__device__ __half g_al[B_ * N_ * C_];
__device__ __half g_wqkv_h[3 * C_ * C_];      // W_qkv^T [3072][1024] hi only
__device__ __half g_wp_h[C_ * C_];            // W_proj^T [1024][1024] hi only

// ---------------------------------------------------------------------------
// PTX helpers (sm_103 base ISA)
// ---------------------------------------------------------------------------
__device__ __forceinline__ uint32_t smem_to_u32(const void* p) {
    uint32_t a;
    asm("{ .reg .u64 t; cvta.to.shared.u64 t, %1; cvt.u32.u64 %0, t; }"
        : "=r"(a) : "l"(p));
    return a;
}

#define CP_ASYNC16(saddr, gptr) \
    asm volatile("cp.async.cg.shared.global [%0], [%1], 16;" \
                 :: "r"(saddr), "l"(gptr) : "memory")
#define CP_COMMIT() asm volatile("cp.async.commit_group;" ::: "memory")
#define CP_WAIT1()  asm volatile("cp.async.wait_group 1;" ::: "memory")
#define CP_WAIT0()  asm volatile("cp.async.wait_group 0;" ::: "memory")

#define LDSM_X4(r0, r1, r2, r3, addr) \
    asm volatile("ldmatrix.sync.aligned.m8n8.x4.shared.b16 {%0,%1,%2,%3}, [%4];" \
                 : "=r"(r0), "=r"(r1), "=r"(r2), "=r"(r3) : "r"(addr))
#define LDSM_X4_T(r0, r1, r2, r3, addr) \
    asm volatile("ldmatrix.sync.aligned.m8n8.x4.trans.shared.b16 {%0,%1,%2,%3}, [%4];" \
                 : "=r"(r0), "=r"(r1), "=r"(r2), "=r"(r3) : "r"(addr))

#define MMAH(d, a, b0, b1) \
    asm volatile("mma.sync.aligned.m16n8k16.row.col.f32.f16.f16.f32 " \
                 "{%0,%1,%2,%3}, {%4,%5,%6,%7}, {%8,%9}, {%0,%1,%2,%3};" \
                 : "+f"((d)[0]), "+f"((d)[1]), "+f"((d)[2]), "+f"((d)[3]) \
                 : "r"((a)[0]), "r"((a)[1]), "r"((a)[2]), "r"((a)[3]), \
                   "r"(b0), "r"(b1))

__device__ __forceinline__ uint32_t pack_h2(float f0, float f1) {
    __half2 h = __floats2half2_rn(f0, f1);
    return *(uint32_t*)&h;
}
__device__ __forceinline__ void pack_split_h(float f0, float f1,
                                             uint32_t& hi, uint32_t& lo) {
    __half h0 = __float2half_rn(f0), h1 = __float2half_rn(f1);
    __half2 Hh; Hh.x = h0; Hh.y = h1;
    __half2 Ll;
    Ll.x = __float2half_rn(f0 - __half2float(h0));
    Ll.y = __float2half_rn(f1 - __half2float(h1));
    hi = *(uint32_t*)&Hh;
    lo = *(uint32_t*)&Ll;
}
__device__ __forceinline__ void split_store2h(__half* hi, __half* lo,
                                              size_t idx, float f0, float f1) {
    uint32_t uh, ul;
    pack_split_h(f0, f1, uh, ul);
    *(uint32_t*)(hi + idx) = uh;
    *(uint32_t*)(lo + idx) = ul;
}

// ---------------------------------------------------------------------------
// fp32 x -> fp16 hi/lo split
// ---------------------------------------------------------------------------
__global__ __launch_bounds__(256) void split_kernel(const float* __restrict__ in, int n4)
{
    int i = blockIdx.x * 256 + threadIdx.x;
    if (i >= n4) return;
    float4 v = ((const float4*)in)[i];
    uint2 H, L;
    pack_split_h(v.x, v.y, H.x, L.x);
    pack_split_h(v.z, v.w, H.y, L.y);
    ((uint2*)g_xh)[i] = H;
    ((uint2*)g_xl)[i] = L;
}

// ---------------------------------------------------------------------------
// fp32 W[K=1024][Ncols] -> transposed fp16 hi [Ncols][1024]
// ---------------------------------------------------------------------------
template<int DST>
__global__ __launch_bounds__(256) void splitT_kernel(const float* __restrict__ in, int Ccols)
{
    __half* hi = (DST == 0) ? g_wqkv_h : g_wp_h;
    __shared__ float t[32][33];
    int tx = threadIdx.x & 31;
    int ty = threadIdx.x >> 5;
    int n_base = blockIdx.x * 32;
    int k_base = blockIdx.y * 32;
#pragma unroll
    for (int i = 0; i < 4; i++) {
        int k = k_base + ty + i * 8;
        t[ty + i * 8][tx] = in[(size_t)k * Ccols + n_base + tx];
    }
    __syncthreads();
#pragma unroll
    for (int i = 0; i < 4; i++) {
        int nn = n_base + ty + i * 8;
        int k = k_base + tx;
        hi[(size_t)nn * C_ + k] = __float2half_rn(t[tx][ty + i * 8]);
    }
}

// ---------------------------------------------------------------------------
// HMMA fp16 2-term GEMM.  CTA tile 128x64, 4 warps (warp tile 32x64), BK=32,
// double-buffered cp.async, 3 CTAs/SM.  Terms: A_hi*B_hi + A_lo*B_hi.
// MODE 0: X @ Wqkv^T -> fp16 q_hi(scaled) / k hi,lo / v hi,lo
// MODE 1: att @ Wp^T -> fp32 out (+bias)
// ---------------------------------------------------------------------------
#define GBK 32
#define LDA 40
#define MAT_A (128 * LDA)                    // 5120 elems
#define MAT_Bm (64 * LDA)                    // 2560 elems
#define STG_ELEMS (2 * MAT_A + MAT_Bm)       // 12800 elems
#define SMEM_GEMM (2 * STG_ELEMS * 2)        // 51200 bytes

template<int MODE>
__global__ __launch_bounds__(128, 3) void mma_gemm_kernel(
    const float* __restrict__ bias, float* __restrict__ outp)
{
    const __half* Ah = (MODE == 0) ? g_xh : g_ah;
    const __half* Al = (MODE == 0) ? g_xl : g_al;
    const __half* Bh = (MODE == 0) ? g_wqkv_h : g_wp_h;

    extern __shared__ __half sm[];
    const uint32_t sbase = smem_to_u32(sm);
    const int tid = threadIdx.x;
    const int wid = tid >> 5, lane = tid & 31;
    const int m0 = blockIdx.y * 128;
    const int n0 = blockIdx.x * 64;

    float acc[2][8][4];
#pragma unroll
    for (int a = 0; a < 2; a++)
#pragma unroll
        for (int b = 0; b < 8; b++)
#pragma unroll
            for (int c = 0; c < 4; c++) acc[a][b][c] = 0.f;

    auto load_stage = [&](int s) {
        const int buf = s & 1;
        const int k0 = s * GBK;
        const uint32_t sb = sbase + (uint32_t)buf * STG_ELEMS * 2;
        // A hi/lo: 512 chunks each, 4 per thread
#pragma unroll
        for (int i = 0; i < 4; i++) {
            int cch = tid + i * 128;           // 0..511
            int r = cch >> 2, kc = cch & 3;
            uint32_t so = (uint32_t)(r * LDA + kc * 8) * 2;
            size_t g = (size_t)(m0 + r) * C_ + k0 + kc * 8;
            CP_ASYNC16(sb + so, Ah + g);
            CP_ASYNC16(sb + (uint32_t)MAT_A * 2 + so, Al + g);
        }
        // B hi: 256 chunks, 2 per thread
#pragma unroll
        for (int i = 0; i < 2; i++) {
            int cch = tid + i * 128;           // 0..255
            int r = cch >> 2, kc = cch & 3;
            uint32_t so = (uint32_t)(r * LDA + kc * 8) * 2;
            size_t g = (size_t)(n0 + r) * C_ + k0 + kc * 8;
            CP_ASYNC16(sb + (uint32_t)(2 * MAT_A) * 2 + so, Bh + g);
        }
        CP_COMMIT();
    };

    constexpr int NS = C_ / GBK;   // 32
    load_stage(0);

    const int lrow = lane & 15;
    const int lk = (lane >> 4) * 8;

    for (int s = 0; s < NS; s++) {
        if (s + 1 < NS) { load_stage(s + 1); CP_WAIT1(); }
        else            { CP_WAIT0(); }
        __syncthreads();

        const uint32_t sb = sbase + (uint32_t)(s & 1) * STG_ELEMS * 2;

#pragma unroll
        for (int kk = 0; kk < GBK; kk += 16) {
            uint32_t ah[2][4], al[2][4], bh[4][4];
#pragma unroll
            for (int mt = 0; mt < 2; mt++) {
                uint32_t off = (uint32_t)((wid * 32 + mt * 16 + lrow) * LDA + kk + lk) * 2;
                LDSM_X4(ah[mt][0], ah[mt][1], ah[mt][2], ah[mt][3], sb + off);
                LDSM_X4(al[mt][0], al[mt][1], al[mt][2], al[mt][3],
                        sb + (uint32_t)MAT_A * 2 + off);
            }
#pragma unroll
            for (int np = 0; np < 4; np++) {
                uint32_t off = (uint32_t)((np * 16 + lrow) * LDA + kk + lk) * 2;
                LDSM_X4(bh[np][0], bh[np][1], bh[np][2], bh[np][3],
                        sb + (uint32_t)(2 * MAT_A) * 2 + off);
            }
            // 2 terms, term-major
#pragma unroll
            for (int mt = 0; mt < 2; mt++)
#pragma unroll
                for (int np = 0; np < 4; np++)
#pragma unroll
                    for (int sel = 0; sel < 2; sel++)
                        MMAH(acc[mt][np * 2 + sel], ah[mt], bh[np][sel], bh[np][2 + sel]);
#pragma unroll
            for (int mt = 0; mt < 2; mt++)
#pragma unroll
                for (int np = 0; np < 4; np++)
#pragma unroll
                    for (int sel = 0; sel < 2; sel++)
                        MMAH(acc[mt][np * 2 + sel], al[mt], bh[np][sel], bh[np][2 + sel]);
        }
        __syncthreads();
    }

    // ---- epilogue ----
#pragma unroll
    for (int mt = 0; mt < 2; mt++) {
#pragma unroll
        for (int nt = 0; nt < 8; nt++) {
            int r = m0 + wid * 32 + mt * 16 + (lane >> 2);
            int c = n0 + nt * 8 + (lane & 3) * 2;
            float b0 = bias[c], b1 = bias[c + 1];
            float s00 = acc[mt][nt][0] + b0, s01 = acc[mt][nt][1] + b1;
            float s10 = acc[mt][nt][2] + b0, s11 = acc[mt][nt][3] + b1;
            if (MODE == 0) {
                int bb = r >> 11, tok = r & 2047;
                int which = c >> 10, ch = c & 1023, h = ch >> 6, d0 = ch & 63;
                size_t base = (((size_t)bb * H_ + h) * N_ + tok) * D_ + d0;
                if (which == 0) {
                    // q: hi only, pre-scaled
                    *(uint32_t*)(g_qh + base) = pack_h2(s00 * SCALE_, s01 * SCALE_);
                    *(uint32_t*)(g_qh + base + 8 * D_) = pack_h2(s10 * SCALE_, s11 * SCALE_);
                } else {
                    __half* dhi = (which == 1) ? g_kh : g_vh;
                    __half* dlo = (which == 1) ? g_kl : g_vl;
                    split_store2h(dhi, dlo, base, s00, s01);
                    split_store2h(dhi, dlo, base + 8 * D_, s10, s11);
                }
            } else {
                *(float2*)(outp + (size_t)r * C_ + c) = make_float2(s00, s01);
                *(float2*)(outp + (size_t)(r + 8) * C_ + c) = make_float2(s10, s11);
            }
        }
    }
}

// ---------------------------------------------------------------------------
// MMA flash attention (fp16).  CTA = (b,h) x 64 queries, 4 warps x 16 rows.
// Key chunks of 64, double-buffered cp.async (Kh,Kl,Vh,Vl), 3 CTAs/SM.
// S = Qh*(Kh+Kl)  (2 terms);  O += (Ph+Pl)*Vh + Ph*Vl  (3 terms).
// ---------------------------------------------------------------------------
#define ALDK 72                            // padded row (elems)
#define AMAT (64 * ALDK)                   // 4608 elems
#define AMAT_B (AMAT * 2)                  // 9216 bytes
#define ASTAGE_B (4 * AMAT_B)              // 36864 bytes
#define SMEM_ATTN (2 * ASTAGE_B)           // 73728 bytes

__global__ __launch_bounds__(128, 3) void attn_mma_kernel()
{
    extern __shared__ __half smx[];
    const uint32_t sb = smem_to_u32(smx);
    const int tid = threadIdx.x;
    const int wid = tid >> 5, lane = tid & 31;
    const int bh = blockIdx.x;
    const int r0t = blockIdx.y * 64;
    const size_t qoff = (size_t)bh * N_ * D_;

    // ---- stage Q tile (64x64 hi) through smem, read fragments ----
#pragma unroll
    for (int i = 0; i < 4; i++) {
        int s = tid + 128 * i;             // 0..511
        int r = s >> 3, c8 = s & 7;
        uint32_t so = (uint32_t)(r * ALDK + c8 * 8) * 2;
        *(uint4*)((char*)smx + so) =
            *(const uint4*)(g_qh + qoff + (size_t)(r0t + r) * D_ + c8 * 8);
    }
    __syncthreads();

    uint32_t qh[4][4];
    {
        const int rb = wid * 16 + (lane & 15);
        const int cb = (lane >> 4) * 8;
#pragma unroll
        for (int kk = 0; kk < 4; kk++) {
            uint32_t addr = sb + (uint32_t)(rb * ALDK + kk * 16 + cb) * 2;
            LDSM_X4(qh[kk][0], qh[kk][1], qh[kk][2], qh[kk][3], addr);
        }
    }
    __syncthreads();

    float accO[8][4];
#pragma unroll
    for (int t = 0; t < 8; t++)
#pragma unroll
        for (int j = 0; j < 4; j++) accO[t][j] = 0.f;
    float mrow[2] = {-CUDART_INF_F, -CUDART_INF_F};
    float lrow[2] = {0.f, 0.f};

    auto load_stage = [&](int c) {
        const uint32_t base = sb + (uint32_t)(c & 1) * ASTAGE_B;
        const int k0 = c * 64;
        const __half* mats[4] = {g_kh, g_kl, g_vh, g_vl};
#pragma unroll
        for (int mat = 0; mat < 4; mat++) {
#pragma unroll
            for (int i = 0; i < 4; i++) {
                int s = tid + 128 * i;     // 0..511
                int r = s >> 3, c8 = s & 7;
                uint32_t so = base + (uint32_t)mat * AMAT_B
                            + (uint32_t)(r * ALDK + c8 * 8) * 2;
                CP_ASYNC16(so, mats[mat] + qoff + (size_t)(k0 + r) * D_ + c8 * 8);
            }
        }
        CP_COMMIT();
    };

    load_stage(0);
    const int lr = lane & 15;
    const int lc = (lane >> 4) * 8;

    for (int c = 0; c < N_ / 64; c++) {
        if (c + 1 < N_ / 64) { load_stage(c + 1); CP_WAIT1(); }
        else                 { CP_WAIT0(); }
        __syncthreads();

        const uint32_t base = sb + (uint32_t)(c & 1) * ASTAGE_B;
        const uint32_t Kh = base, Kl = base + AMAT_B;
        const uint32_t Vh = base + 2 * AMAT_B, Vl = base + 3 * AMAT_B;

        // ---- S = Qh (Kh + Kl)^T  (2 terms, term-major) ----
        float accS[8][4];
#pragma unroll
        for (int t = 0; t < 8; t++)
#pragma unroll
            for (int j = 0; j < 4; j++) accS[t][j] = 0.f;

#pragma unroll
        for (int kk = 0; kk < 4; kk++) {
#pragma unroll
            for (int hp = 0; hp < 2; hp++) {
                const int ng0 = hp * 2, ng1 = hp * 2 + 1;
                uint32_t ha[4], la[4], hb[4], lb[4];
                uint32_t offa = (uint32_t)((ng0 * 16 + lr) * ALDK + kk * 16 + lc) * 2;
                uint32_t offb = (uint32_t)((ng1 * 16 + lr) * ALDK + kk * 16 + lc) * 2;
                LDSM_X4(ha[0], ha[1], ha[2], ha[3], Kh + offa);
                LDSM_X4(la[0], la[1], la[2], la[3], Kl + offa);
                LDSM_X4(hb[0], hb[1], hb[2], hb[3], Kh + offb);
                LDSM_X4(lb[0], lb[1], lb[2], lb[3], Kl + offb);
                MMAH(accS[2 * ng0],     qh[kk], ha[0], ha[2]);
                MMAH(accS[2 * ng0 + 1], qh[kk], ha[1], ha[3]);
                MMAH(accS[2 * ng1],     qh[kk], hb[0], hb[2]);
                MMAH(accS[2 * ng1 + 1], qh[kk], hb[1], hb[3]);
                MMAH(accS[2 * ng0],     qh[kk], la[0], la[2]);
                MMAH(accS[2 * ng0 + 1], qh[kk], la[1], la[3]);
                MMAH(accS[2 * ng1],     qh[kk], lb[0], lb[2]);
                MMAH(accS[2 * ng1 + 1], qh[kk], lb[1], lb[3]);
            }
        }

        // ---- online softmax (q already scaled by 0.125) ----
#pragma unroll
        for (int p = 0; p < 2; p++) {
            float vm = accS[0][2 * p];
#pragma unroll
            for (int t = 0; t < 8; t++) {
                vm = fmaxf(vm, accS[t][2 * p]);
                vm = fmaxf(vm, accS[t][2 * p + 1]);
            }
            vm = fmaxf(vm, __shfl_xor_sync(0xffffffffu, vm, 1));
            vm = fmaxf(vm, __shfl_xor_sync(0xffffffffu, vm, 2));
            float mn = fmaxf(mrow[p], vm);
            float alpha = __expf(mrow[p] - mn);
            float sum = 0.f;
#pragma unroll
            for (int t = 0; t < 8; t++) {
                float e0 = __expf(accS[t][2 * p]     - mn);
                float e1 = __expf(accS[t][2 * p + 1] - mn);
                accS[t][2 * p] = e0; accS[t][2 * p + 1] = e1;
                sum += e0 + e1;
            }
            sum += __shfl_xor_sync(0xffffffffu, sum, 1);
            sum += __shfl_xor_sync(0xffffffffu, sum, 2);
            lrow[p] = lrow[p] * alpha + sum;
            mrow[p] = mn;
#pragma unroll
            for (int t = 0; t < 8; t++) {
                accO[t][2 * p]     *= alpha;
                accO[t][2 * p + 1] *= alpha;
            }
        }

        // ---- O += (Ph+Pl) Vh + Ph Vl  (3 terms, term-major) ----
#pragma unroll
        for (int kk = 0; kk < 4; kk++) {
            uint32_t ph[4], pl[4];
            pack_split_h(accS[2 * kk][0],     accS[2 * kk][1],     ph[0], pl[0]);
            pack_split_h(accS[2 * kk][2],     accS[2 * kk][3],     ph[1], pl[1]);
            pack_split_h(accS[2 * kk + 1][0], accS[2 * kk + 1][1], ph[2], pl[2]);
            pack_split_h(accS[2 * kk + 1][2], accS[2 * kk + 1][3], ph[3], pl[3]);
#pragma unroll
            for (int dp = 0; dp < 2; dp++) {
                const int dg0 = dp * 2, dg1 = dp * 2 + 1;
                uint32_t va[4], wa[4], vb[4], wb[4];
                uint32_t offa = (uint32_t)((kk * 16 + lr) * ALDK + dg0 * 16 + lc) * 2;
                uint32_t offb = (uint32_t)((kk * 16 + lr) * ALDK + dg1 * 16 + lc) * 2;
                LDSM_X4_T(va[0], va[1], va[2], va[3], Vh + offa);
                LDSM_X4_T(wa[0], wa[1], wa[2], wa[3], Vl + offa);
                LDSM_X4_T(vb[0], vb[1], vb[2], vb[3], Vh + offb);
                LDSM_X4_T(wb[0], wb[1], wb[2], wb[3], Vl + offb);
                MMAH(accO[2 * dg0],     ph, va[0], va[1]);
                MMAH(accO[2 * dg0 + 1], ph, va[2], va[3]);
                MMAH(accO[2 * dg1],     ph, vb[0], vb[1]);
                MMAH(accO[2 * dg1 + 1], ph, vb[2], vb[3]);
                MMAH(accO[2 * dg0],     pl, va[0], va[1]);
                MMAH(accO[2 * dg0 + 1], pl, va[2], va[3]);
                MMAH(accO[2 * dg1],     pl, vb[0], vb[1]);
                MMAH(accO[2 * dg1 + 1], pl, vb[2], vb[3]);
                MMAH(accO[2 * dg0],     ph, wa[0], wa[1]);
                MMAH(accO[2 * dg0 + 1], ph, wa[2], wa[3]);
                MMAH(accO[2 * dg1],     ph, wb[0], wb[1]);
                MMAH(accO[2 * dg1 + 1], ph, wb[2], wb[3]);
            }
        }
        __syncthreads();
    }

    // ---- epilogue: normalize, split to fp16 hi/lo in [B][N][C] ----
    const int b = bh >> 4;
    const int h = bh & 15;
    const float inv0 = 1.0f / lrow[0];
    const float inv1 = 1.0f / lrow[1];
    const int row0 = r0t + wid * 16 + (lane >> 2);
#pragma unroll
    for (int t = 0; t < 8; t++) {
        int col = h * 64 + t * 8 + (lane & 3) * 2;
        split_store2h(g_ah, g_al, ((size_t)b * N_ + row0) * C_ + col,
                      accO[t][0] * inv0, accO[t][1] * inv0);
        split_store2h(g_ah, g_al, ((size_t)b * N_ + row0 + 8) * C_ + col,
                      accO[t][2] * inv1, accO[t][3] * inv1);
    }
}

// ---------------------------------------------------------------------------
extern "C" void kernel_launch(void* const* d_in, const int* in_sizes, int n_in,
                              void* d_out, int out_size)
{
    const float* x      = (const float*)d_in[0];
    const float* w_qkv  = (const float*)d_in[1];
    const float* b_qkv  = (const float*)d_in[2];
    const float* w_proj = (const float*)d_in[3];
    const float* b_proj = (const float*)d_in[4];
    float* out = (float*)d_out;

    cudaFuncSetAttribute(mma_gemm_kernel<0>,
                         cudaFuncAttributeMaxDynamicSharedMemorySize, SMEM_GEMM);
    cudaFuncSetAttribute(mma_gemm_kernel<1>,
                         cudaFuncAttributeMaxDynamicSharedMemorySize, SMEM_GEMM);
    cudaFuncSetAttribute(attn_mma_kernel,
                         cudaFuncAttributeMaxDynamicSharedMemorySize, SMEM_ATTN);

    // 1. Split conversions
    {
        int n4 = B_ * N_ * C_ / 4;
        split_kernel<<<(n4 + 255) / 256, 256>>>(x, n4);
        dim3 g1(3 * C_ / 32, C_ / 32);
        splitT_kernel<0><<<g1, 256>>>(w_qkv, 3 * C_);
        dim3 g2(C_ / 32, C_ / 32);
        splitT_kernel<1><<<g2, 256>>>(w_proj, C_);
    }

    // 2. QKV GEMM -> fp16 q_hi(scaled) / k hi,lo / v hi,lo
    {
        dim3 grid(3 * C_ / 64, (B_ * N_) / 128);   // (48, 64)
        mma_gemm_kernel<0><<<grid, 128, SMEM_GEMM>>>(b_qkv, nullptr);
    }

    // 3. MMA flash attention -> g_ah/g_al
    {
        dim3 grid(B_ * H_, N_ / 64);               // (64, 32)
        attn_mma_kernel<<<grid, 128, SMEM_ATTN>>>();
    }

    // 4. Projection GEMM -> out
    {
        dim3 grid(C_ / 64, (B_ * N_) / 128);       // (16, 64)
        mma_gemm_kernel<1><<<grid, 128, SMEM_GEMM>>>(b_proj, out);
    }
}

// round 10
// speedup vs baseline: 1.4795x; 1.0756x over previous
#include <cuda_runtime.h>
#include <cuda_fp16.h>
#include <math_constants.h>
#include <cstdint>

// Problem constants
#define B_ 4
#define N_ 2048
#define C_ 1024
#define H_ 16
#define D_ 64
#define SCALE_ 0.125f   // 1/sqrt(64)

// ---------------------------------------------------------------------------
// Scratch (device globals: allocation-free).  fp16 hi/lo scheme:
//   GEMM A-side (activations): hi+lo.  GEMM B-side (weights): hi only.
//   Attention: Q hi only, K hi+lo, V hi only, att-out hi+lo.
// ---------------------------------------------------------------------------
__device__ __half g_qh[B_ * H_ * N_ * D_];    // q pre-scaled by 0.125
__device__ __half g_kh[B_ * H_ * N_ * D_];
__device__ __half g_kl[B_ * H_ * N_ * D_];
__device__ __half g_vh[B_ * H_ * N_ * D_];

__device__ __half g_xh[B_ * N_ * C_];         // X split [8192][1024]
__device__ __half g_xl[B_ * N_ * C_];
__device__ __half g_ah[B_ * N_ * C_];         // attention out split
__device__ __half g_al[B_ * N_ * C_];
__device__ __half g_wqkv_h[3 * C_ * C_];      // W_qkv^T [3072][1024] hi only
__device__ __half g_wp_h[C_ * C_];            // W_proj^T [1024][1024] hi only

// ---------------------------------------------------------------------------
// PTX helpers (sm_103 base ISA)
// ---------------------------------------------------------------------------
__device__ __forceinline__ uint32_t smem_to_u32(const void* p) {
    uint32_t a;
    asm("{ .reg .u64 t; cvta.to.shared.u64 t, %1; cvt.u32.u64 %0, t; }"
        : "=r"(a) : "l"(p));
    return a;
}

#define CP_ASYNC16(saddr, gptr) \
    asm volatile("cp.async.cg.shared.global [%0], [%1], 16;" \
                 :: "r"(saddr), "l"(gptr) : "memory")
#define CP_COMMIT() asm volatile("cp.async.commit_group;" ::: "memory")
#define CP_WAIT1()  asm volatile("cp.async.wait_group 1;" ::: "memory")
#define CP_WAIT0()  asm volatile("cp.async.wait_group 0;" ::: "memory")

#define LDSM_X4(r0, r1, r2, r3, addr) \
    asm volatile("ldmatrix.sync.aligned.m8n8.x4.shared.b16 {%0,%1,%2,%3}, [%4];" \
                 : "=r"(r0), "=r"(r1), "=r"(r2), "=r"(r3) : "r"(addr))
#define LDSM_X4_T(r0, r1, r2, r3, addr) \
    asm volatile("ldmatrix.sync.aligned.m8n8.x4.trans.shared.b16 {%0,%1,%2,%3}, [%4];" \
                 : "=r"(r0), "=r"(r1), "=r"(r2), "=r"(r3) : "r"(addr))

#define MMAH(d, a, b0, b1) \
    asm volatile("mma.sync.aligned.m16n8k16.row.col.f32.f16.f16.f32 " \
                 "{%0,%1,%2,%3}, {%4,%5,%6,%7}, {%8,%9}, {%0,%1,%2,%3};" \
                 : "+f"((d)[0]), "+f"((d)[1]), "+f"((d)[2]), "+f"((d)[3]) \
                 : "r"((a)[0]), "r"((a)[1]), "r"((a)[2]), "r"((a)[3]), \
                   "r"(b0), "r"(b1))

__device__ __forceinline__ uint32_t pack_h2(float f0, float f1) {
    __half2 h = __floats2half2_rn(f0, f1);
    return *(uint32_t*)&h;
}
__device__ __forceinline__ void pack_split_h(float f0, float f1,
                                             uint32_t& hi, uint32_t& lo) {
    __half h0 = __float2half_rn(f0), h1 = __float2half_rn(f1);
    __half2 Hh; Hh.x = h0; Hh.y = h1;
    __half2 Ll;
    Ll.x = __float2half_rn(f0 - __half2float(h0));
    Ll.y = __float2half_rn(f1 - __half2float(h1));
    hi = *(uint32_t*)&Hh;
    lo = *(uint32_t*)&Ll;
}
__device__ __forceinline__ void split_store2h(__half* hi, __half* lo,
                                              size_t idx, float f0, float f1) {
    uint32_t uh, ul;
    pack_split_h(f0, f1, uh, ul);
    *(uint32_t*)(hi + idx) = uh;
    *(uint32_t*)(lo + idx) = ul;
}

// ---------------------------------------------------------------------------
// fp32 x -> fp16 hi/lo split
// ---------------------------------------------------------------------------
__global__ __launch_bounds__(256) void split_kernel(const float* __restrict__ in, int n4)
{
    int i = blockIdx.x * 256 + threadIdx.x;
    if (i >= n4) return;
    float4 v = ((const float4*)in)[i];
    uint2 H, L;
    pack_split_h(v.x, v.y, H.x, L.x);
    pack_split_h(v.z, v.w, H.y, L.y);
    ((uint2*)g_xh)[i] = H;
    ((uint2*)g_xl)[i] = L;
}

// ---------------------------------------------------------------------------
// fp32 W[K=1024][Ncols] -> transposed fp16 hi [Ncols][1024]
// ---------------------------------------------------------------------------
template<int DST>
__global__ __launch_bounds__(256) void splitT_kernel(const float* __restrict__ in, int Ccols)
{
    __half* hi = (DST == 0) ? g_wqkv_h : g_wp_h;
    __shared__ float t[32][33];
    int tx = threadIdx.x & 31;
    int ty = threadIdx.x >> 5;
    int n_base = blockIdx.x * 32;
    int k_base = blockIdx.y * 32;
#pragma unroll
    for (int i = 0; i < 4; i++) {
        int k = k_base + ty + i * 8;
        t[ty + i * 8][tx] = in[(size_t)k * Ccols + n_base + tx];
    }
    __syncthreads();
#pragma unroll
    for (int i = 0; i < 4; i++) {
        int nn = n_base + ty + i * 8;
        int k = k_base + tx;
        hi[(size_t)nn * C_ + k] = __float2half_rn(t[tx][ty + i * 8]);
    }
}

// ---------------------------------------------------------------------------
// HMMA fp16 2-term GEMM.  CTA tile 128x64, 4 warps (warp tile 32x64), BK=32,
// double-buffered cp.async, 3 CTAs/SM.  Terms: A_hi*B_hi + A_lo*B_hi.
// MODE 0: X @ Wqkv^T -> fp16 q_hi(scaled) / k hi,lo / v hi
// MODE 1: att @ Wp^T -> fp32 out (+bias)
// ---------------------------------------------------------------------------
#define GBK 32
#define LDA 40
#define MAT_A (128 * LDA)                    // 5120 elems
#define MAT_Bm (64 * LDA)                    // 2560 elems
#define STG_ELEMS (2 * MAT_A + MAT_Bm)       // 12800 elems
#define SMEM_GEMM (2 * STG_ELEMS * 2)        // 51200 bytes

template<int MODE>
__global__ __launch_bounds__(128, 3) void mma_gemm_kernel(
    const float* __restrict__ bias, float* __restrict__ outp)
{
    const __half* Ah = (MODE == 0) ? g_xh : g_ah;
    const __half* Al = (MODE == 0) ? g_xl : g_al;
    const __half* Bh = (MODE == 0) ? g_wqkv_h : g_wp_h;

    extern __shared__ __half sm[];
    const uint32_t sbase = smem_to_u32(sm);
    const int tid = threadIdx.x;
    const int wid = tid >> 5, lane = tid & 31;
    const int m0 = blockIdx.y * 128;
    const int n0 = blockIdx.x * 64;

    float acc[2][8][4];
#pragma unroll
    for (int a = 0; a < 2; a++)
#pragma unroll
        for (int b = 0; b < 8; b++)
#pragma unroll
            for (int c = 0; c < 4; c++) acc[a][b][c] = 0.f;

    auto load_stage = [&](int s) {
        const int buf = s & 1;
        const int k0 = s * GBK;
        const uint32_t sb = sbase + (uint32_t)buf * STG_ELEMS * 2;
#pragma unroll
        for (int i = 0; i < 4; i++) {
            int cch = tid + i * 128;           // 0..511
            int r = cch >> 2, kc = cch & 3;
            uint32_t so = (uint32_t)(r * LDA + kc * 8) * 2;
            size_t g = (size_t)(m0 + r) * C_ + k0 + kc * 8;
            CP_ASYNC16(sb + so, Ah + g);
            CP_ASYNC16(sb + (uint32_t)MAT_A * 2 + so, Al + g);
        }
#pragma unroll
        for (int i = 0; i < 2; i++) {
            int cch = tid + i * 128;           // 0..255
            int r = cch >> 2, kc = cch & 3;
            uint32_t so = (uint32_t)(r * LDA + kc * 8) * 2;
            size_t g = (size_t)(n0 + r) * C_ + k0 + kc * 8;
            CP_ASYNC16(sb + (uint32_t)(2 * MAT_A) * 2 + so, Bh + g);
        }
        CP_COMMIT();
    };

    constexpr int NS = C_ / GBK;   // 32
    load_stage(0);

    const int lrow = lane & 15;
    const int lk = (lane >> 4) * 8;

    for (int s = 0; s < NS; s++) {
        if (s + 1 < NS) { load_stage(s + 1); CP_WAIT1(); }
        else            { CP_WAIT0(); }
        __syncthreads();

        const uint32_t sb = sbase + (uint32_t)(s & 1) * STG_ELEMS * 2;

#pragma unroll
        for (int kk = 0; kk < GBK; kk += 16) {
            uint32_t ah[2][4], al[2][4], bh[4][4];
#pragma unroll
            for (int mt = 0; mt < 2; mt++) {
                uint32_t off = (uint32_t)((wid * 32 + mt * 16 + lrow) * LDA + kk + lk) * 2;
                LDSM_X4(ah[mt][0], ah[mt][1], ah[mt][2], ah[mt][3], sb + off);
                LDSM_X4(al[mt][0], al[mt][1], al[mt][2], al[mt][3],
                        sb + (uint32_t)MAT_A * 2 + off);
            }
#pragma unroll
            for (int np = 0; np < 4; np++) {
                uint32_t off = (uint32_t)((np * 16 + lrow) * LDA + kk + lk) * 2;
                LDSM_X4(bh[np][0], bh[np][1], bh[np][2], bh[np][3],
                        sb + (uint32_t)(2 * MAT_A) * 2 + off);
            }
#pragma unroll
            for (int mt = 0; mt < 2; mt++)
#pragma unroll
                for (int np = 0; np < 4; np++)
#pragma unroll
                    for (int sel = 0; sel < 2; sel++)
                        MMAH(acc[mt][np * 2 + sel], ah[mt], bh[np][sel], bh[np][2 + sel]);
#pragma unroll
            for (int mt = 0; mt < 2; mt++)
#pragma unroll
                for (int np = 0; np < 4; np++)
#pragma unroll
                    for (int sel = 0; sel < 2; sel++)
                        MMAH(acc[mt][np * 2 + sel], al[mt], bh[np][sel], bh[np][2 + sel]);
        }
        __syncthreads();
    }

    // ---- epilogue ----
#pragma unroll
    for (int mt = 0; mt < 2; mt++) {
#pragma unroll
        for (int nt = 0; nt < 8; nt++) {
            int r = m0 + wid * 32 + mt * 16 + (lane >> 2);
            int c = n0 + nt * 8 + (lane & 3) * 2;
            float b0 = bias[c], b1 = bias[c + 1];
            float s00 = acc[mt][nt][0] + b0, s01 = acc[mt][nt][1] + b1;
            float s10 = acc[mt][nt][2] + b0, s11 = acc[mt][nt][3] + b1;
            if (MODE == 0) {
                int bb = r >> 11, tok = r & 2047;
                int which = c >> 10, ch = c & 1023, h = ch >> 6, d0 = ch & 63;
                size_t base = (((size_t)bb * H_ + h) * N_ + tok) * D_ + d0;
                if (which == 0) {
                    *(uint32_t*)(g_qh + base) = pack_h2(s00 * SCALE_, s01 * SCALE_);
                    *(uint32_t*)(g_qh + base + 8 * D_) = pack_h2(s10 * SCALE_, s11 * SCALE_);
                } else if (which == 1) {
                    split_store2h(g_kh, g_kl, base, s00, s01);
                    split_store2h(g_kh, g_kl, base + 8 * D_, s10, s11);
                } else {
                    *(uint32_t*)(g_vh + base) = pack_h2(s00, s01);
                    *(uint32_t*)(g_vh + base + 8 * D_) = pack_h2(s10, s11);
                }
            } else {
                *(float2*)(outp + (size_t)r * C_ + c) = make_float2(s00, s01);
                *(float2*)(outp + (size_t)(r + 8) * C_ + c) = make_float2(s10, s11);
            }
        }
    }
}

// ---------------------------------------------------------------------------
// MMA flash attention (fp16).  CTA = (b,h) x 64 queries, 4 warps x 16 rows.
// Key chunks of 64, double-buffered cp.async (Kh,Kl,Vh), 4 CTAs/SM.
// S = Qh*(Kh+Kl)  (2 terms);  O += (Ph+Pl)*Vh  (2 terms).
// ---------------------------------------------------------------------------
#define ALDK 72                            // padded row (elems)
#define AMAT (64 * ALDK)                   // 4608 elems
#define AMAT_B (AMAT * 2)                  // 9216 bytes
#define ASTAGE_B (3 * AMAT_B)              // 27648 bytes
#define SMEM_ATTN (2 * ASTAGE_B)           // 55296 bytes

__global__ __launch_bounds__(128, 4) void attn_mma_kernel()
{
    extern __shared__ __half smx[];
    const uint32_t sb = smem_to_u32(smx);
    const int tid = threadIdx.x;
    const int wid = tid >> 5, lane = tid & 31;
    const int bh = blockIdx.x;
    const int r0t = blockIdx.y * 64;
    const size_t qoff = (size_t)bh * N_ * D_;

    // ---- stage Q tile (64x64 hi) through smem, read fragments ----
#pragma unroll
    for (int i = 0; i < 4; i++) {
        int s = tid + 128 * i;             // 0..511
        int r = s >> 3, c8 = s & 7;
        uint32_t so = (uint32_t)(r * ALDK + c8 * 8) * 2;
        *(uint4*)((char*)smx + so) =
            *(const uint4*)(g_qh + qoff + (size_t)(r0t + r) * D_ + c8 * 8);
    }
    __syncthreads();

    uint32_t qh[4][4];
    {
        const int rb = wid * 16 + (lane & 15);
        const int cb = (lane >> 4) * 8;
#pragma unroll
        for (int kk = 0; kk < 4; kk++) {
            uint32_t addr = sb + (uint32_t)(rb * ALDK + kk * 16 + cb) * 2;
            LDSM_X4(qh[kk][0], qh[kk][1], qh[kk][2], qh[kk][3], addr);
        }
    }
    __syncthreads();

    float accO[8][4];
#pragma unroll
    for (int t = 0; t < 8; t++)
#pragma unroll
        for (int j = 0; j < 4; j++) accO[t][j] = 0.f;
    float mrow[2] = {-CUDART_INF_F, -CUDART_INF_F};
    float lrow[2] = {0.f, 0.f};

    auto load_stage = [&](int c) {
        const uint32_t base = sb + (uint32_t)(c & 1) * ASTAGE_B;
        const int k0 = c * 64;
        const __half* mats[3] = {g_kh, g_kl, g_vh};
#pragma unroll
        for (int mat = 0; mat < 3; mat++) {
#pragma unroll
            for (int i = 0; i < 4; i++) {
                int s = tid + 128 * i;     // 0..511
                int r = s >> 3, c8 = s & 7;
                uint32_t so = base + (uint32_t)mat * AMAT_B
                            + (uint32_t)(r * ALDK + c8 * 8) * 2;
                CP_ASYNC16(so, mats[mat] + qoff + (size_t)(k0 + r) * D_ + c8 * 8);
            }
        }
        CP_COMMIT();
    };

    load_stage(0);
    const int lr = lane & 15;
    const int lc = (lane >> 4) * 8;

    for (int c = 0; c < N_ / 64; c++) {
        if (c + 1 < N_ / 64) { load_stage(c + 1); CP_WAIT1(); }
        else                 { CP_WAIT0(); }
        __syncthreads();

        const uint32_t base = sb + (uint32_t)(c & 1) * ASTAGE_B;
        const uint32_t Kh = base, Kl = base + AMAT_B;
        const uint32_t Vh = base + 2 * AMAT_B;

        // ---- S = Qh (Kh + Kl)^T  (2 terms, term-major) ----
        float accS[8][4];
#pragma unroll
        for (int t = 0; t < 8; t++)
#pragma unroll
            for (int j = 0; j < 4; j++) accS[t][j] = 0.f;

#pragma unroll
        for (int kk = 0; kk < 4; kk++) {
#pragma unroll
            for (int hp = 0; hp < 2; hp++) {
                const int ng0 = hp * 2, ng1 = hp * 2 + 1;
                uint32_t ha[4], la[4], hb[4], lb[4];
                uint32_t offa = (uint32_t)((ng0 * 16 + lr) * ALDK + kk * 16 + lc) * 2;
                uint32_t offb = (uint32_t)((ng1 * 16 + lr) * ALDK + kk * 16 + lc) * 2;
                LDSM_X4(ha[0], ha[1], ha[2], ha[3], Kh + offa);
                LDSM_X4(la[0], la[1], la[2], la[3], Kl + offa);
                LDSM_X4(hb[0], hb[1], hb[2], hb[3], Kh + offb);
                LDSM_X4(lb[0], lb[1], lb[2], lb[3], Kl + offb);
                MMAH(accS[2 * ng0],     qh[kk], ha[0], ha[2]);
                MMAH(accS[2 * ng0 + 1], qh[kk], ha[1], ha[3]);
                MMAH(accS[2 * ng1],     qh[kk], hb[0], hb[2]);
                MMAH(accS[2 * ng1 + 1], qh[kk], hb[1], hb[3]);
                MMAH(accS[2 * ng0],     qh[kk], la[0], la[2]);
                MMAH(accS[2 * ng0 + 1], qh[kk], la[1], la[3]);
                MMAH(accS[2 * ng1],     qh[kk], lb[0], lb[2]);
                MMAH(accS[2 * ng1 + 1], qh[kk], lb[1], lb[3]);
            }
        }

        // ---- online softmax (q already scaled by 0.125) ----
#pragma unroll
        for (int p = 0; p < 2; p++) {
            float vm = accS[0][2 * p];
#pragma unroll
            for (int t = 0; t < 8; t++) {
                vm = fmaxf(vm, accS[t][2 * p]);
                vm = fmaxf(vm, accS[t][2 * p + 1]);
            }
            vm = fmaxf(vm, __shfl_xor_sync(0xffffffffu, vm, 1));
            vm = fmaxf(vm, __shfl_xor_sync(0xffffffffu, vm, 2));
            float mn = fmaxf(mrow[p], vm);
            float alpha = __expf(mrow[p] - mn);
            float sum = 0.f;
#pragma unroll
            for (int t = 0; t < 8; t++) {
                float e0 = __expf(accS[t][2 * p]     - mn);
                float e1 = __expf(accS[t][2 * p + 1] - mn);
                accS[t][2 * p] = e0; accS[t][2 * p + 1] = e1;
                sum += e0 + e1;
            }
            sum += __shfl_xor_sync(0xffffffffu, sum, 1);
            sum += __shfl_xor_sync(0xffffffffu, sum, 2);
            lrow[p] = lrow[p] * alpha + sum;
            mrow[p] = mn;
#pragma unroll
            for (int t = 0; t < 8; t++) {
                accO[t][2 * p]     *= alpha;
                accO[t][2 * p + 1] *= alpha;
            }
        }

        // ---- O += (Ph + Pl) Vh  (2 terms, term-major) ----
#pragma unroll
        for (int kk = 0; kk < 4; kk++) {
            uint32_t ph[4], pl[4];
            pack_split_h(accS[2 * kk][0],     accS[2 * kk][1],     ph[0], pl[0]);
            pack_split_h(accS[2 * kk][2],     accS[2 * kk][3],     ph[1], pl[1]);
            pack_split_h(accS[2 * kk + 1][0], accS[2 * kk + 1][1], ph[2], pl[2]);
            pack_split_h(accS[2 * kk + 1][2], accS[2 * kk + 1][3], ph[3], pl[3]);
#pragma unroll
            for (int dp = 0; dp < 2; dp++) {
                const int dg0 = dp * 2, dg1 = dp * 2 + 1;
                uint32_t va[4], vb[4];
                uint32_t offa = (uint32_t)((kk * 16 + lr) * ALDK + dg0 * 16 + lc) * 2;
                uint32_t offb = (uint32_t)((kk * 16 + lr) * ALDK + dg1 * 16 + lc) * 2;
                LDSM_X4_T(va[0], va[1], va[2], va[3], Vh + offa);
                LDSM_X4_T(vb[0], vb[1], vb[2], vb[3], Vh + offb);
                MMAH(accO[2 * dg0],     ph, va[0], va[1]);
                MMAH(accO[2 * dg0 + 1], ph, va[2], va[3]);
                MMAH(accO[2 * dg1],     ph, vb[0], vb[1]);
                MMAH(accO[2 * dg1 + 1], ph, vb[2], vb[3]);
                MMAH(accO[2 * dg0],     pl, va[0], va[1]);
                MMAH(accO[2 * dg0 + 1], pl, va[2], va[3]);
                MMAH(accO[2 * dg1],     pl, vb[0], vb[1]);
                MMAH(accO[2 * dg1 + 1], pl, vb[2], vb[3]);
            }
        }
        __syncthreads();
    }

    // ---- epilogue: normalize, split to fp16 hi/lo in [B][N][C] ----
    const int b = bh >> 4;
    const int h = bh & 15;
    const float inv0 = 1.0f / lrow[0];
    const float inv1 = 1.0f / lrow[1];
    const int row0 = r0t + wid * 16 + (lane >> 2);
#pragma unroll
    for (int t = 0; t < 8; t++) {
        int col = h * 64 + t * 8 + (lane & 3) * 2;
        split_store2h(g_ah, g_al, ((size_t)b * N_ + row0) * C_ + col,
                      accO[t][0] * inv0, accO[t][1] * inv0);
        split_store2h(g_ah, g_al, ((size_t)b * N_ + row0 + 8) * C_ + col,
                      accO[t][2] * inv1, accO[t][3] * inv1);
    }
}

// ---------------------------------------------------------------------------
extern "C" void kernel_launch(void* const* d_in, const int* in_sizes, int n_in,
                              void* d_out, int out_size)
{
    const float* x      = (const float*)d_in[0];
    const float* w_qkv  = (const float*)d_in[1];
    const float* b_qkv  = (const float*)d_in[2];
    const float* w_proj = (const float*)d_in[3];
    const float* b_proj = (const float*)d_in[4];
    float* out = (float*)d_out;

    cudaFuncSetAttribute(mma_gemm_kernel<0>,
                         cudaFuncAttributeMaxDynamicSharedMemorySize, SMEM_GEMM);
    cudaFuncSetAttribute(mma_gemm_kernel<1>,
                         cudaFuncAttributeMaxDynamicSharedMemorySize, SMEM_GEMM);
    cudaFuncSetAttribute(attn_mma_kernel,
                         cudaFuncAttributeMaxDynamicSharedMemorySize, SMEM_ATTN);

    // 1. Split conversions
    {
        int n4 = B_ * N_ * C_ / 4;
        split_kernel<<<(n4 + 255) / 256, 256>>>(x, n4);
        dim3 g1(3 * C_ / 32, C_ / 32);
        splitT_kernel<0><<<g1, 256>>>(w_qkv, 3 * C_);
        dim3 g2(C_ / 32, C_ / 32);
        splitT_kernel<1><<<g2, 256>>>(w_proj, C_);
    }

    // 2. QKV GEMM -> fp16 q_hi(scaled) / k hi,lo / v hi
    {
        dim3 grid(3 * C_ / 64, (B_ * N_) / 128);   // (48, 64)
        mma_gemm_kernel<0><<<grid, 128, SMEM_GEMM>>>(b_qkv, nullptr);
    }

    // 3. MMA flash attention -> g_ah/g_al
    {
        dim3 grid(B_ * H_, N_ / 64);               // (64, 32)
        attn_mma_kernel<<<grid, 128, SMEM_ATTN>>>();
    }

    // 4. Projection GEMM -> out
    {
        dim3 grid(C_ / 64, (B_ * N_) / 128);       // (16, 64)
        mma_gemm_kernel<1><<<grid, 128, SMEM_GEMM>>>(b_proj, out);
    }
}

// round 11
// speedup vs baseline: 1.8090x; 1.2227x over previous
#include <cuda_runtime.h>
#include <cuda_fp16.h>
#include <math_constants.h>
#include <cstdint>

// Problem constants
#define B_ 4
#define N_ 2048
#define C_ 1024
#define H_ 16
#define D_ 64
#define SCALE_ 0.125f   // 1/sqrt(64)

// ---------------------------------------------------------------------------
// Scratch (device globals: allocation-free).  fp16 scheme:
//   GEMM A-side (x, att-out): hi+lo.  Weights: hi only.
//   Attention operands Q/K/V: hi only (error budget: 6 x 2.4e-4 in quadrature).
// ---------------------------------------------------------------------------
__device__ __half g_qh[B_ * H_ * N_ * D_];    // q pre-scaled by 0.125
__device__ __half g_kh[B_ * H_ * N_ * D_];
__device__ __half g_vh[B_ * H_ * N_ * D_];

__device__ __half g_xh[B_ * N_ * C_];         // X split [8192][1024]
__device__ __half g_xl[B_ * N_ * C_];
__device__ __half g_ah[B_ * N_ * C_];         // attention out split
__device__ __half g_al[B_ * N_ * C_];
__device__ __half g_wqkv_h[3 * C_ * C_];      // W_qkv^T [3072][1024] hi only
__device__ __half g_wp_h[C_ * C_];            // W_proj^T [1024][1024] hi only

// ---------------------------------------------------------------------------
// PTX helpers (sm_103 base ISA)
// ---------------------------------------------------------------------------
__device__ __forceinline__ uint32_t smem_to_u32(const void* p) {
    uint32_t a;
    asm("{ .reg .u64 t; cvta.to.shared.u64 t, %1; cvt.u32.u64 %0, t; }"
        : "=r"(a) : "l"(p));
    return a;
}

#define CP_ASYNC16(saddr, gptr) \
    asm volatile("cp.async.cg.shared.global [%0], [%1], 16;" \
                 :: "r"(saddr), "l"(gptr) : "memory")
#define CP_COMMIT() asm volatile("cp.async.commit_group;" ::: "memory")
#define CP_WAIT1()  asm volatile("cp.async.wait_group 1;" ::: "memory")
#define CP_WAIT0()  asm volatile("cp.async.wait_group 0;" ::: "memory")

#define LDSM_X4(r0, r1, r2, r3, addr) \
    asm volatile("ldmatrix.sync.aligned.m8n8.x4.shared.b16 {%0,%1,%2,%3}, [%4];" \
                 : "=r"(r0), "=r"(r1), "=r"(r2), "=r"(r3) : "r"(addr))
#define LDSM_X4_T(r0, r1, r2, r3, addr) \
    asm volatile("ldmatrix.sync.aligned.m8n8.x4.trans.shared.b16 {%0,%1,%2,%3}, [%4];" \
                 : "=r"(r0), "=r"(r1), "=r"(r2), "=r"(r3) : "r"(addr))

#define MMAH(d, a, b0, b1) \
    asm volatile("mma.sync.aligned.m16n8k16.row.col.f32.f16.f16.f32 " \
                 "{%0,%1,%2,%3}, {%4,%5,%6,%7}, {%8,%9}, {%0,%1,%2,%3};" \
                 : "+f"((d)[0]), "+f"((d)[1]), "+f"((d)[2]), "+f"((d)[3]) \
                 : "r"((a)[0]), "r"((a)[1]), "r"((a)[2]), "r"((a)[3]), \
                   "r"(b0), "r"(b1))

__device__ __forceinline__ uint32_t pack_h2(float f0, float f1) {
    __half2 h = __floats2half2_rn(f0, f1);
    return *(uint32_t*)&h;
}
__device__ __forceinline__ void pack_split_h(float f0, float f1,
                                             uint32_t& hi, uint32_t& lo) {
    __half h0 = __float2half_rn(f0), h1 = __float2half_rn(f1);
    __half2 Hh; Hh.x = h0; Hh.y = h1;
    __half2 Ll;
    Ll.x = __float2half_rn(f0 - __half2float(h0));
    Ll.y = __float2half_rn(f1 - __half2float(h1));
    hi = *(uint32_t*)&Hh;
    lo = *(uint32_t*)&Ll;
}
__device__ __forceinline__ void split_store2h(__half* hi, __half* lo,
                                              size_t idx, float f0, float f1) {
    uint32_t uh, ul;
    pack_split_h(f0, f1, uh, ul);
    *(uint32_t*)(hi + idx) = uh;
    *(uint32_t*)(lo + idx) = ul;
}

// ---------------------------------------------------------------------------
// fp32 x -> fp16 hi/lo split
// ---------------------------------------------------------------------------
__global__ __launch_bounds__(256) void split_kernel(const float* __restrict__ in, int n4)
{
    int i = blockIdx.x * 256 + threadIdx.x;
    if (i >= n4) return;
    float4 v = ((const float4*)in)[i];
    uint2 H, L;
    pack_split_h(v.x, v.y, H.x, L.x);
    pack_split_h(v.z, v.w, H.y, L.y);
    ((uint2*)g_xh)[i] = H;
    ((uint2*)g_xl)[i] = L;
}

// ---------------------------------------------------------------------------
// fp32 W[K=1024][Ncols] -> transposed fp16 hi [Ncols][1024]
// ---------------------------------------------------------------------------
template<int DST>
__global__ __launch_bounds__(256) void splitT_kernel(const float* __restrict__ in, int Ccols)
{
    __half* hi = (DST == 0) ? g_wqkv_h : g_wp_h;
    __shared__ float t[32][33];
    int tx = threadIdx.x & 31;
    int ty = threadIdx.x >> 5;
    int n_base = blockIdx.x * 32;
    int k_base = blockIdx.y * 32;
#pragma unroll
    for (int i = 0; i < 4; i++) {
        int k = k_base + ty + i * 8;
        t[ty + i * 8][tx] = in[(size_t)k * Ccols + n_base + tx];
    }
    __syncthreads();
#pragma unroll
    for (int i = 0; i < 4; i++) {
        int nn = n_base + ty + i * 8;
        int k = k_base + tx;
        hi[(size_t)nn * C_ + k] = __float2half_rn(t[tx][ty + i * 8]);
    }
}

// ---------------------------------------------------------------------------
// HMMA fp16 2-term GEMM.  CTA tile 128x64, 4 warps (warp tile 32x64), BK=32,
// double-buffered cp.async, 3 CTAs/SM.  Terms: A_hi*B_hi + A_lo*B_hi.
// MODE 0: X @ Wqkv^T -> fp16 q_hi(scaled) / k_hi / v_hi
// MODE 1: att @ Wp^T -> fp32 out (+bias)
// ---------------------------------------------------------------------------
#define GBK 32
#define LDA 40
#define MAT_A (128 * LDA)                    // 5120 elems
#define MAT_Bm (64 * LDA)                    // 2560 elems
#define STG_ELEMS (2 * MAT_A + MAT_Bm)       // 12800 elems
#define SMEM_GEMM (2 * STG_ELEMS * 2)        // 51200 bytes

template<int MODE>
__global__ __launch_bounds__(128, 3) void mma_gemm_kernel(
    const float* __restrict__ bias, float* __restrict__ outp)
{
    const __half* Ah = (MODE == 0) ? g_xh : g_ah;
    const __half* Al = (MODE == 0) ? g_xl : g_al;
    const __half* Bh = (MODE == 0) ? g_wqkv_h : g_wp_h;

    extern __shared__ __half sm[];
    const uint32_t sbase = smem_to_u32(sm);
    const int tid = threadIdx.x;
    const int wid = tid >> 5, lane = tid & 31;
    const int m0 = blockIdx.y * 128;
    const int n0 = blockIdx.x * 64;

    float acc[2][8][4];
#pragma unroll
    for (int a = 0; a < 2; a++)
#pragma unroll
        for (int b = 0; b < 8; b++)
#pragma unroll
            for (int c = 0; c < 4; c++) acc[a][b][c] = 0.f;

    auto load_stage = [&](int s) {
        const int buf = s & 1;
        const int k0 = s * GBK;
        const uint32_t sb = sbase + (uint32_t)buf * STG_ELEMS * 2;
#pragma unroll
        for (int i = 0; i < 4; i++) {
            int cch = tid + i * 128;           // 0..511
            int r = cch >> 2, kc = cch & 3;
            uint32_t so = (uint32_t)(r * LDA + kc * 8) * 2;
            size_t g = (size_t)(m0 + r) * C_ + k0 + kc * 8;
            CP_ASYNC16(sb + so, Ah + g);
            CP_ASYNC16(sb + (uint32_t)MAT_A * 2 + so, Al + g);
        }
#pragma unroll
        for (int i = 0; i < 2; i++) {
            int cch = tid + i * 128;           // 0..255
            int r = cch >> 2, kc = cch & 3;
            uint32_t so = (uint32_t)(r * LDA + kc * 8) * 2;
            size_t g = (size_t)(n0 + r) * C_ + k0 + kc * 8;
            CP_ASYNC16(sb + (uint32_t)(2 * MAT_A) * 2 + so, Bh + g);
        }
        CP_COMMIT();
    };

    constexpr int NS = C_ / GBK;   // 32
    load_stage(0);

    const int lrow = lane & 15;
    const int lk = (lane >> 4) * 8;

    for (int s = 0; s < NS; s++) {
        if (s + 1 < NS) { load_stage(s + 1); CP_WAIT1(); }
        else            { CP_WAIT0(); }
        __syncthreads();

        const uint32_t sb = sbase + (uint32_t)(s & 1) * STG_ELEMS * 2;

#pragma unroll
        for (int kk = 0; kk < GBK; kk += 16) {
            uint32_t ah[2][4], al[2][4], bh[4][4];
#pragma unroll
            for (int mt = 0; mt < 2; mt++) {
                uint32_t off = (uint32_t)((wid * 32 + mt * 16 + lrow) * LDA + kk + lk) * 2;
                LDSM_X4(ah[mt][0], ah[mt][1], ah[mt][2], ah[mt][3], sb + off);
                LDSM_X4(al[mt][0], al[mt][1], al[mt][2], al[mt][3],
                        sb + (uint32_t)MAT_A * 2 + off);
            }
#pragma unroll
            for (int np = 0; np < 4; np++) {
                uint32_t off = (uint32_t)((np * 16 + lrow) * LDA + kk + lk) * 2;
                LDSM_X4(bh[np][0], bh[np][1], bh[np][2], bh[np][3],
                        sb + (uint32_t)(2 * MAT_A) * 2 + off);
            }
#pragma unroll
            for (int mt = 0; mt < 2; mt++)
#pragma unroll
                for (int np = 0; np < 4; np++)
#pragma unroll
                    for (int sel = 0; sel < 2; sel++)
                        MMAH(acc[mt][np * 2 + sel], ah[mt], bh[np][sel], bh[np][2 + sel]);
#pragma unroll
            for (int mt = 0; mt < 2; mt++)
#pragma unroll
                for (int np = 0; np < 4; np++)
#pragma unroll
                    for (int sel = 0; sel < 2; sel++)
                        MMAH(acc[mt][np * 2 + sel], al[mt], bh[np][sel], bh[np][2 + sel]);
        }
        __syncthreads();
    }

    // ---- epilogue ----
#pragma unroll
    for (int mt = 0; mt < 2; mt++) {
#pragma unroll
        for (int nt = 0; nt < 8; nt++) {
            int r = m0 + wid * 32 + mt * 16 + (lane >> 2);
            int c = n0 + nt * 8 + (lane & 3) * 2;
            float b0 = bias[c], b1 = bias[c + 1];
            float s00 = acc[mt][nt][0] + b0, s01 = acc[mt][nt][1] + b1;
            float s10 = acc[mt][nt][2] + b0, s11 = acc[mt][nt][3] + b1;
            if (MODE == 0) {
                int bb = r >> 11, tok = r & 2047;
                int which = c >> 10, ch = c & 1023, h = ch >> 6, d0 = ch & 63;
                size_t base = (((size_t)bb * H_ + h) * N_ + tok) * D_ + d0;
                __half* dst = (which == 0) ? g_qh : (which == 1) ? g_kh : g_vh;
                float sc = (which == 0) ? SCALE_ : 1.0f;
                *(uint32_t*)(dst + base) = pack_h2(s00 * sc, s01 * sc);
                *(uint32_t*)(dst + base + 8 * D_) = pack_h2(s10 * sc, s11 * sc);
            } else {
                *(float2*)(outp + (size_t)r * C_ + c) = make_float2(s00, s01);
                *(float2*)(outp + (size_t)(r + 8) * C_ + c) = make_float2(s10, s11);
            }
        }
    }
}

// ---------------------------------------------------------------------------
// MMA flash attention (fp16, single-term).  CTA = (b,h) x 64 queries,
// 4 warps x 16 rows.  Key chunks of 64, double-buffered cp.async (Kh,Vh),
// 4 CTAs/SM.  S = Qh*Kh  (1 MMA);  O += Ph*Vh  (1 MMA).
// ---------------------------------------------------------------------------
#define ALDK 72                            // padded row (elems)
#define AMAT (64 * ALDK)                   // 4608 elems
#define AMAT_B (AMAT * 2)                  // 9216 bytes
#define ASTAGE_B (2 * AMAT_B)              // 18432 bytes
#define SMEM_ATTN (2 * ASTAGE_B)           // 36864 bytes

__global__ __launch_bounds__(128, 4) void attn_mma_kernel()
{
    extern __shared__ __half smx[];
    const uint32_t sb = smem_to_u32(smx);
    const int tid = threadIdx.x;
    const int wid = tid >> 5, lane = tid & 31;
    const int bh = blockIdx.x;
    const int r0t = blockIdx.y * 64;
    const size_t qoff = (size_t)bh * N_ * D_;

    // ---- stage Q tile (64x64 hi) through smem, read fragments ----
#pragma unroll
    for (int i = 0; i < 4; i++) {
        int s = tid + 128 * i;             // 0..511
        int r = s >> 3, c8 = s & 7;
        uint32_t so = (uint32_t)(r * ALDK + c8 * 8) * 2;
        *(uint4*)((char*)smx + so) =
            *(const uint4*)(g_qh + qoff + (size_t)(r0t + r) * D_ + c8 * 8);
    }
    __syncthreads();

    uint32_t qh[4][4];
    {
        const int rb = wid * 16 + (lane & 15);
        const int cb = (lane >> 4) * 8;
#pragma unroll
        for (int kk = 0; kk < 4; kk++) {
            uint32_t addr = sb + (uint32_t)(rb * ALDK + kk * 16 + cb) * 2;
            LDSM_X4(qh[kk][0], qh[kk][1], qh[kk][2], qh[kk][3], addr);
        }
    }
    __syncthreads();

    float accO[8][4];
#pragma unroll
    for (int t = 0; t < 8; t++)
#pragma unroll
        for (int j = 0; j < 4; j++) accO[t][j] = 0.f;
    float mrow[2] = {-CUDART_INF_F, -CUDART_INF_F};
    float lrow[2] = {0.f, 0.f};

    auto load_stage = [&](int c) {
        const uint32_t base = sb + (uint32_t)(c & 1) * ASTAGE_B;
        const int k0 = c * 64;
        const __half* mats[2] = {g_kh, g_vh};
#pragma unroll
        for (int mat = 0; mat < 2; mat++) {
#pragma unroll
            for (int i = 0; i < 4; i++) {
                int s = tid + 128 * i;     // 0..511
                int r = s >> 3, c8 = s & 7;
                uint32_t so = base + (uint32_t)mat * AMAT_B
                            + (uint32_t)(r * ALDK + c8 * 8) * 2;
                CP_ASYNC16(so, mats[mat] + qoff + (size_t)(k0 + r) * D_ + c8 * 8);
            }
        }
        CP_COMMIT();
    };

    load_stage(0);
    const int lr = lane & 15;
    const int lc = (lane >> 4) * 8;

    for (int c = 0; c < N_ / 64; c++) {
        if (c + 1 < N_ / 64) { load_stage(c + 1); CP_WAIT1(); }
        else                 { CP_WAIT0(); }
        __syncthreads();

        const uint32_t base = sb + (uint32_t)(c & 1) * ASTAGE_B;
        const uint32_t Kh = base;
        const uint32_t Vh = base + AMAT_B;

        // ---- S = Qh Kh^T  (1 MMA per tile) ----
        float accS[8][4];
#pragma unroll
        for (int t = 0; t < 8; t++)
#pragma unroll
            for (int j = 0; j < 4; j++) accS[t][j] = 0.f;

#pragma unroll
        for (int kk = 0; kk < 4; kk++) {
#pragma unroll
            for (int hp = 0; hp < 2; hp++) {
                const int ng0 = hp * 2, ng1 = hp * 2 + 1;
                uint32_t ha[4], hb[4];
                uint32_t offa = (uint32_t)((ng0 * 16 + lr) * ALDK + kk * 16 + lc) * 2;
                uint32_t offb = (uint32_t)((ng1 * 16 + lr) * ALDK + kk * 16 + lc) * 2;
                LDSM_X4(ha[0], ha[1], ha[2], ha[3], Kh + offa);
                LDSM_X4(hb[0], hb[1], hb[2], hb[3], Kh + offb);
                MMAH(accS[2 * ng0],     qh[kk], ha[0], ha[2]);
                MMAH(accS[2 * ng0 + 1], qh[kk], ha[1], ha[3]);
                MMAH(accS[2 * ng1],     qh[kk], hb[0], hb[2]);
                MMAH(accS[2 * ng1 + 1], qh[kk], hb[1], hb[3]);
            }
        }

        // ---- online softmax (q already scaled by 0.125) ----
#pragma unroll
        for (int p = 0; p < 2; p++) {
            float vm = accS[0][2 * p];
#pragma unroll
            for (int t = 0; t < 8; t++) {
                vm = fmaxf(vm, accS[t][2 * p]);
                vm = fmaxf(vm, accS[t][2 * p + 1]);
            }
            vm = fmaxf(vm, __shfl_xor_sync(0xffffffffu, vm, 1));
            vm = fmaxf(vm, __shfl_xor_sync(0xffffffffu, vm, 2));
            float mn = fmaxf(mrow[p], vm);
            float alpha = __expf(mrow[p] - mn);
            float sum = 0.f;
#pragma unroll
            for (int t = 0; t < 8; t++) {
                float e0 = __expf(accS[t][2 * p]     - mn);
                float e1 = __expf(accS[t][2 * p + 1] - mn);
                accS[t][2 * p] = e0; accS[t][2 * p + 1] = e1;
                sum += e0 + e1;
            }
            sum += __shfl_xor_sync(0xffffffffu, sum, 1);
            sum += __shfl_xor_sync(0xffffffffu, sum, 2);
            lrow[p] = lrow[p] * alpha + sum;
            mrow[p] = mn;
#pragma unroll
            for (int t = 0; t < 8; t++) {
                accO[t][2 * p]     *= alpha;
                accO[t][2 * p + 1] *= alpha;
            }
        }

        // ---- O += Ph Vh  (1 MMA per tile) ----
#pragma unroll
        for (int kk = 0; kk < 4; kk++) {
            uint32_t ph[4];
            ph[0] = pack_h2(accS[2 * kk][0],     accS[2 * kk][1]);
            ph[1] = pack_h2(accS[2 * kk][2],     accS[2 * kk][3]);
            ph[2] = pack_h2(accS[2 * kk + 1][0], accS[2 * kk + 1][1]);
            ph[3] = pack_h2(accS[2 * kk + 1][2], accS[2 * kk + 1][3]);
#pragma unroll
            for (int dp = 0; dp < 2; dp++) {
                const int dg0 = dp * 2, dg1 = dp * 2 + 1;
                uint32_t va[4], vb[4];
                uint32_t offa = (uint32_t)((kk * 16 + lr) * ALDK + dg0 * 16 + lc) * 2;
                uint32_t offb = (uint32_t)((kk * 16 + lr) * ALDK + dg1 * 16 + lc) * 2;
                LDSM_X4_T(va[0], va[1], va[2], va[3], Vh + offa);
                LDSM_X4_T(vb[0], vb[1], vb[2], vb[3], Vh + offb);
                MMAH(accO[2 * dg0],     ph, va[0], va[1]);
                MMAH(accO[2 * dg0 + 1], ph, va[2], va[3]);
                MMAH(accO[2 * dg1],     ph, vb[0], vb[1]);
                MMAH(accO[2 * dg1 + 1], ph, vb[2], vb[3]);
            }
        }
        __syncthreads();
    }

    // ---- epilogue: normalize, split to fp16 hi/lo in [B][N][C] ----
    const int b = bh >> 4;
    const int h = bh & 15;
    const float inv0 = 1.0f / lrow[0];
    const float inv1 = 1.0f / lrow[1];
    const int row0 = r0t + wid * 16 + (lane >> 2);
#pragma unroll
    for (int t = 0; t < 8; t++) {
        int col = h * 64 + t * 8 + (lane & 3) * 2;
        split_store2h(g_ah, g_al, ((size_t)b * N_ + row0) * C_ + col,
                      accO[t][0] * inv0, accO[t][1] * inv0);
        split_store2h(g_ah, g_al, ((size_t)b * N_ + row0 + 8) * C_ + col,
                      accO[t][2] * inv1, accO[t][3] * inv1);
    }
}

// ---------------------------------------------------------------------------
extern "C" void kernel_launch(void* const* d_in, const int* in_sizes, int n_in,
                              void* d_out, int out_size)
{
    const float* x      = (const float*)d_in[0];
    const float* w_qkv  = (const float*)d_in[1];
    const float* b_qkv  = (const float*)d_in[2];
    const float* w_proj = (const float*)d_in[3];
    const float* b_proj = (const float*)d_in[4];
    float* out = (float*)d_out;

    cudaFuncSetAttribute(mma_gemm_kernel<0>,
                         cudaFuncAttributeMaxDynamicSharedMemorySize, SMEM_GEMM);
    cudaFuncSetAttribute(mma_gemm_kernel<1>,
                         cudaFuncAttributeMaxDynamicSharedMemorySize, SMEM_GEMM);
    cudaFuncSetAttribute(attn_mma_kernel,
                         cudaFuncAttributeMaxDynamicSharedMemorySize, SMEM_ATTN);

    // 1. Split conversions
    {
        int n4 = B_ * N_ * C_ / 4;
        split_kernel<<<(n4 + 255) / 256, 256>>>(x, n4);
        dim3 g1(3 * C_ / 32, C_ / 32);
        splitT_kernel<0><<<g1, 256>>>(w_qkv, 3 * C_);
        dim3 g2(C_ / 32, C_ / 32);
        splitT_kernel<1><<<g2, 256>>>(w_proj, C_);
    }

    // 2. QKV GEMM -> fp16 q_hi(scaled) / k_hi / v_hi
    {
        dim3 grid(3 * C_ / 64, (B_ * N_) / 128);   // (48, 64)
        mma_gemm_kernel<0><<<grid, 128, SMEM_GEMM>>>(b_qkv, nullptr);
    }

    // 3. MMA flash attention -> g_ah/g_al
    {
        dim3 grid(B_ * H_, N_ / 64);               // (64, 32)
        attn_mma_kernel<<<grid, 128, SMEM_ATTN>>>();
    }

    // 4. Projection GEMM -> out
    {
        dim3 grid(C_ / 64, (B_ * N_) / 128);       // (16, 64)
        mma_gemm_kernel<1><<<grid, 128, SMEM_GEMM>>>(b_proj, out);
    }
}

// round 12
// speedup vs baseline: 2.6309x; 1.4543x over previous
#include <cuda_runtime.h>
#include <cuda_fp16.h>
#include <math_constants.h>
#include <cstdint>

// Problem constants
#define B_ 4
#define N_ 2048
#define C_ 1024
#define H_ 16
#define D_ 64
#define SCALE_ 0.125f   // 1/sqrt(64)

// ---------------------------------------------------------------------------
// Scratch (device globals: allocation-free).  Pure fp16 pipeline:
// every matmul single-term.  Error budget ~7 x 2.4e-4 sources in quadrature
// ~ 6.4e-4 < 1e-3.
// ---------------------------------------------------------------------------
__device__ __half g_qh[B_ * H_ * N_ * D_];    // q pre-scaled by 0.125
__device__ __half g_kh[B_ * H_ * N_ * D_];
__device__ __half g_vh[B_ * H_ * N_ * D_];

__device__ __half g_xh[B_ * N_ * C_];         // X fp16 [8192][1024]
__device__ __half g_ah[B_ * N_ * C_];         // attention out fp16
__device__ __half g_wqkv_h[3 * C_ * C_];      // W_qkv^T [3072][1024]
__device__ __half g_wp_h[C_ * C_];            // W_proj^T [1024][1024]

// ---------------------------------------------------------------------------
// PTX helpers (sm_103 base ISA)
// ---------------------------------------------------------------------------
__device__ __forceinline__ uint32_t smem_to_u32(const void* p) {
    uint32_t a;
    asm("{ .reg .u64 t; cvta.to.shared.u64 t, %1; cvt.u32.u64 %0, t; }"
        : "=r"(a) : "l"(p));
    return a;
}

#define CP_ASYNC16(saddr, gptr) \
    asm volatile("cp.async.cg.shared.global [%0], [%1], 16;" \
                 :: "r"(saddr), "l"(gptr) : "memory")
#define CP_COMMIT() asm volatile("cp.async.commit_group;" ::: "memory")
#define CP_WAIT1()  asm volatile("cp.async.wait_group 1;" ::: "memory")
#define CP_WAIT0()  asm volatile("cp.async.wait_group 0;" ::: "memory")

#define LDSM_X4(r0, r1, r2, r3, addr) \
    asm volatile("ldmatrix.sync.aligned.m8n8.x4.shared.b16 {%0,%1,%2,%3}, [%4];" \
                 : "=r"(r0), "=r"(r1), "=r"(r2), "=r"(r3) : "r"(addr))
#define LDSM_X4_T(r0, r1, r2, r3, addr) \
    asm volatile("ldmatrix.sync.aligned.m8n8.x4.trans.shared.b16 {%0,%1,%2,%3}, [%4];" \
                 : "=r"(r0), "=r"(r1), "=r"(r2), "=r"(r3) : "r"(addr))

#define MMAH(d, a, b0, b1) \
    asm volatile("mma.sync.aligned.m16n8k16.row.col.f32.f16.f16.f32 " \
                 "{%0,%1,%2,%3}, {%4,%5,%6,%7}, {%8,%9}, {%0,%1,%2,%3};" \
                 : "+f"((d)[0]), "+f"((d)[1]), "+f"((d)[2]), "+f"((d)[3]) \
                 : "r"((a)[0]), "r"((a)[1]), "r"((a)[2]), "r"((a)[3]), \
                   "r"(b0), "r"(b1))

__device__ __forceinline__ uint32_t pack_h2(float f0, float f1) {
    __half2 h = __floats2half2_rn(f0, f1);
    return *(uint32_t*)&h;
}

// ---------------------------------------------------------------------------
// fp32 x -> fp16
// ---------------------------------------------------------------------------
__global__ __launch_bounds__(256) void split_kernel(const float* __restrict__ in, int n4)
{
    int i = blockIdx.x * 256 + threadIdx.x;
    if (i >= n4) return;
    float4 v = ((const float4*)in)[i];
    uint2 H;
    H.x = pack_h2(v.x, v.y);
    H.y = pack_h2(v.z, v.w);
    ((uint2*)g_xh)[i] = H;
}

// ---------------------------------------------------------------------------
// fp32 W[K=1024][Ncols] -> transposed fp16 [Ncols][1024]
// ---------------------------------------------------------------------------
template<int DST>
__global__ __launch_bounds__(256) void splitT_kernel(const float* __restrict__ in, int Ccols)
{
    __half* hi = (DST == 0) ? g_wqkv_h : g_wp_h;
    __shared__ float t[32][33];
    int tx = threadIdx.x & 31;
    int ty = threadIdx.x >> 5;
    int n_base = blockIdx.x * 32;
    int k_base = blockIdx.y * 32;
#pragma unroll
    for (int i = 0; i < 4; i++) {
        int k = k_base + ty + i * 8;
        t[ty + i * 8][tx] = in[(size_t)k * Ccols + n_base + tx];
    }
    __syncthreads();
#pragma unroll
    for (int i = 0; i < 4; i++) {
        int nn = n_base + ty + i * 8;
        int k = k_base + tx;
        hi[(size_t)nn * C_ + k] = __float2half_rn(t[tx][ty + i * 8]);
    }
}

// ---------------------------------------------------------------------------
// HMMA fp16 single-term GEMM.  CTA tile 128x64, 4 warps (warp tile 32x64),
// BK=32, double-buffered cp.async, 4 CTAs/SM.
// MODE 0: X @ Wqkv^T -> fp16 q(scaled) / k / v
// MODE 1: att @ Wp^T -> fp32 out (+bias)
// ---------------------------------------------------------------------------
#define GBK 32
#define LDA 40
#define MAT_A (128 * LDA)                    // 5120 elems
#define MAT_Bm (64 * LDA)                    // 2560 elems
#define STG_ELEMS (MAT_A + MAT_Bm)           // 7680 elems
#define SMEM_GEMM (2 * STG_ELEMS * 2)        // 30720 bytes

template<int MODE>
__global__ __launch_bounds__(128, 4) void mma_gemm_kernel(
    const float* __restrict__ bias, float* __restrict__ outp)
{
    const __half* Ah = (MODE == 0) ? g_xh : g_ah;
    const __half* Bh = (MODE == 0) ? g_wqkv_h : g_wp_h;

    extern __shared__ __half sm[];
    const uint32_t sbase = smem_to_u32(sm);
    const int tid = threadIdx.x;
    const int wid = tid >> 5, lane = tid & 31;
    const int m0 = blockIdx.y * 128;
    const int n0 = blockIdx.x * 64;

    float acc[2][8][4];
#pragma unroll
    for (int a = 0; a < 2; a++)
#pragma unroll
        for (int b = 0; b < 8; b++)
#pragma unroll
            for (int c = 0; c < 4; c++) acc[a][b][c] = 0.f;

    auto load_stage = [&](int s) {
        const int buf = s & 1;
        const int k0 = s * GBK;
        const uint32_t sb = sbase + (uint32_t)buf * STG_ELEMS * 2;
#pragma unroll
        for (int i = 0; i < 4; i++) {
            int cch = tid + i * 128;           // 0..511
            int r = cch >> 2, kc = cch & 3;
            uint32_t so = (uint32_t)(r * LDA + kc * 8) * 2;
            CP_ASYNC16(sb + so, Ah + (size_t)(m0 + r) * C_ + k0 + kc * 8);
        }
#pragma unroll
        for (int i = 0; i < 2; i++) {
            int cch = tid + i * 128;           // 0..255
            int r = cch >> 2, kc = cch & 3;
            uint32_t so = (uint32_t)(r * LDA + kc * 8) * 2;
            CP_ASYNC16(sb + (uint32_t)MAT_A * 2 + so,
                       Bh + (size_t)(n0 + r) * C_ + k0 + kc * 8);
        }
        CP_COMMIT();
    };

    constexpr int NS = C_ / GBK;   // 32
    load_stage(0);

    const int lrow = lane & 15;
    const int lk = (lane >> 4) * 8;

    for (int s = 0; s < NS; s++) {
        if (s + 1 < NS) { load_stage(s + 1); CP_WAIT1(); }
        else            { CP_WAIT0(); }
        __syncthreads();

        const uint32_t sb = sbase + (uint32_t)(s & 1) * STG_ELEMS * 2;

#pragma unroll
        for (int kk = 0; kk < GBK; kk += 16) {
            uint32_t ah[2][4], bh[4][4];
#pragma unroll
            for (int mt = 0; mt < 2; mt++) {
                uint32_t off = (uint32_t)((wid * 32 + mt * 16 + lrow) * LDA + kk + lk) * 2;
                LDSM_X4(ah[mt][0], ah[mt][1], ah[mt][2], ah[mt][3], sb + off);
            }
#pragma unroll
            for (int np = 0; np < 4; np++) {
                uint32_t off = (uint32_t)((np * 16 + lrow) * LDA + kk + lk) * 2;
                LDSM_X4(bh[np][0], bh[np][1], bh[np][2], bh[np][3],
                        sb + (uint32_t)MAT_A * 2 + off);
            }
#pragma unroll
            for (int mt = 0; mt < 2; mt++)
#pragma unroll
                for (int np = 0; np < 4; np++)
#pragma unroll
                    for (int sel = 0; sel < 2; sel++)
                        MMAH(acc[mt][np * 2 + sel], ah[mt], bh[np][sel], bh[np][2 + sel]);
        }
        __syncthreads();
    }

    // ---- epilogue ----
#pragma unroll
    for (int mt = 0; mt < 2; mt++) {
#pragma unroll
        for (int nt = 0; nt < 8; nt++) {
            int r = m0 + wid * 32 + mt * 16 + (lane >> 2);
            int c = n0 + nt * 8 + (lane & 3) * 2;
            float b0 = bias[c], b1 = bias[c + 1];
            float s00 = acc[mt][nt][0] + b0, s01 = acc[mt][nt][1] + b1;
            float s10 = acc[mt][nt][2] + b0, s11 = acc[mt][nt][3] + b1;
            if (MODE == 0) {
                int bb = r >> 11, tok = r & 2047;
                int which = c >> 10, ch = c & 1023, h = ch >> 6, d0 = ch & 63;
                size_t base = (((size_t)bb * H_ + h) * N_ + tok) * D_ + d0;
                __half* dst = (which == 0) ? g_qh : (which == 1) ? g_kh : g_vh;
                float sc = (which == 0) ? SCALE_ : 1.0f;
                *(uint32_t*)(dst + base) = pack_h2(s00 * sc, s01 * sc);
                *(uint32_t*)(dst + base + 8 * D_) = pack_h2(s10 * sc, s11 * sc);
            } else {
                *(float2*)(outp + (size_t)r * C_ + c) = make_float2(s00, s01);
                *(float2*)(outp + (size_t)(r + 8) * C_ + c) = make_float2(s10, s11);
            }
        }
    }
}

// ---------------------------------------------------------------------------
// MMA flash attention (fp16, single-term).  CTA = (b,h) x 64 queries,
// 4 warps x 16 rows.  Key chunks of 64, double-buffered cp.async (Kh,Vh),
// 4 CTAs/SM.  S = Qh*Kh;  O += Ph*Vh.
// ---------------------------------------------------------------------------
#define ALDK 72                            // padded row (elems)
#define AMAT (64 * ALDK)                   // 4608 elems
#define AMAT_B (AMAT * 2)                  // 9216 bytes
#define ASTAGE_B (2 * AMAT_B)              // 18432 bytes
#define SMEM_ATTN (2 * ASTAGE_B)           // 36864 bytes

__global__ __launch_bounds__(128, 4) void attn_mma_kernel()
{
    extern __shared__ __half smx[];
    const uint32_t sb = smem_to_u32(smx);
    const int tid = threadIdx.x;
    const int wid = tid >> 5, lane = tid & 31;
    const int bh = blockIdx.x;
    const int r0t = blockIdx.y * 64;
    const size_t qoff = (size_t)bh * N_ * D_;

    // ---- stage Q tile (64x64) through smem, read fragments ----
#pragma unroll
    for (int i = 0; i < 4; i++) {
        int s = tid + 128 * i;             // 0..511
        int r = s >> 3, c8 = s & 7;
        uint32_t so = (uint32_t)(r * ALDK + c8 * 8) * 2;
        *(uint4*)((char*)smx + so) =
            *(const uint4*)(g_qh + qoff + (size_t)(r0t + r) * D_ + c8 * 8);
    }
    __syncthreads();

    uint32_t qh[4][4];
    {
        const int rb = wid * 16 + (lane & 15);
        const int cb = (lane >> 4) * 8;
#pragma unroll
        for (int kk = 0; kk < 4; kk++) {
            uint32_t addr = sb + (uint32_t)(rb * ALDK + kk * 16 + cb) * 2;
            LDSM_X4(qh[kk][0], qh[kk][1], qh[kk][2], qh[kk][3], addr);
        }
    }
    __syncthreads();

    float accO[8][4];
#pragma unroll
    for (int t = 0; t < 8; t++)
#pragma unroll
        for (int j = 0; j < 4; j++) accO[t][j] = 0.f;
    float mrow[2] = {-CUDART_INF_F, -CUDART_INF_F};
    float lrow[2] = {0.f, 0.f};

    auto load_stage = [&](int c) {
        const uint32_t base = sb + (uint32_t)(c & 1) * ASTAGE_B;
        const int k0 = c * 64;
        const __half* mats[2] = {g_kh, g_vh};
#pragma unroll
        for (int mat = 0; mat < 2; mat++) {
#pragma unroll
            for (int i = 0; i < 4; i++) {
                int s = tid + 128 * i;     // 0..511
                int r = s >> 3, c8 = s & 7;
                uint32_t so = base + (uint32_t)mat * AMAT_B
                            + (uint32_t)(r * ALDK + c8 * 8) * 2;
                CP_ASYNC16(so, mats[mat] + qoff + (size_t)(k0 + r) * D_ + c8 * 8);
            }
        }
        CP_COMMIT();
    };

    load_stage(0);
    const int lr = lane & 15;
    const int lc = (lane >> 4) * 8;

    for (int c = 0; c < N_ / 64; c++) {
        if (c + 1 < N_ / 64) { load_stage(c + 1); CP_WAIT1(); }
        else                 { CP_WAIT0(); }
        __syncthreads();

        const uint32_t base = sb + (uint32_t)(c & 1) * ASTAGE_B;
        const uint32_t Kh = base;
        const uint32_t Vh = base + AMAT_B;

        // ---- S = Qh Kh^T ----
        float accS[8][4];
#pragma unroll
        for (int t = 0; t < 8; t++)
#pragma unroll
            for (int j = 0; j < 4; j++) accS[t][j] = 0.f;

#pragma unroll
        for (int kk = 0; kk < 4; kk++) {
#pragma unroll
            for (int hp = 0; hp < 2; hp++) {
                const int ng0 = hp * 2, ng1 = hp * 2 + 1;
                uint32_t ha[4], hb[4];
                uint32_t offa = (uint32_t)((ng0 * 16 + lr) * ALDK + kk * 16 + lc) * 2;
                uint32_t offb = (uint32_t)((ng1 * 16 + lr) * ALDK + kk * 16 + lc) * 2;
                LDSM_X4(ha[0], ha[1], ha[2], ha[3], Kh + offa);
                LDSM_X4(hb[0], hb[1], hb[2], hb[3], Kh + offb);
                MMAH(accS[2 * ng0],     qh[kk], ha[0], ha[2]);
                MMAH(accS[2 * ng0 + 1], qh[kk], ha[1], ha[3]);
                MMAH(accS[2 * ng1],     qh[kk], hb[0], hb[2]);
                MMAH(accS[2 * ng1 + 1], qh[kk], hb[1], hb[3]);
            }
        }

        // ---- online softmax (q already scaled by 0.125) ----
#pragma unroll
        for (int p = 0; p < 2; p++) {
            float vm = accS[0][2 * p];
#pragma unroll
            for (int t = 0; t < 8; t++) {
                vm = fmaxf(vm, accS[t][2 * p]);
                vm = fmaxf(vm, accS[t][2 * p + 1]);
            }
            vm = fmaxf(vm, __shfl_xor_sync(0xffffffffu, vm, 1));
            vm = fmaxf(vm, __shfl_xor_sync(0xffffffffu, vm, 2));
            float mn = fmaxf(mrow[p], vm);
            float alpha = __expf(mrow[p] - mn);
            float sum = 0.f;
#pragma unroll
            for (int t = 0; t < 8; t++) {
                float e0 = __expf(accS[t][2 * p]     - mn);
                float e1 = __expf(accS[t][2 * p + 1] - mn);
                accS[t][2 * p] = e0; accS[t][2 * p + 1] = e1;
                sum += e0 + e1;
            }
            sum += __shfl_xor_sync(0xffffffffu, sum, 1);
            sum += __shfl_xor_sync(0xffffffffu, sum, 2);
            lrow[p] = lrow[p] * alpha + sum;
            mrow[p] = mn;
#pragma unroll
            for (int t = 0; t < 8; t++) {
                accO[t][2 * p]     *= alpha;
                accO[t][2 * p + 1] *= alpha;
            }
        }

        // ---- O += Ph Vh ----
#pragma unroll
        for (int kk = 0; kk < 4; kk++) {
            uint32_t ph[4];
            ph[0] = pack_h2(accS[2 * kk][0],     accS[2 * kk][1]);
            ph[1] = pack_h2(accS[2 * kk][2],     accS[2 * kk][3]);
            ph[2] = pack_h2(accS[2 * kk + 1][0], accS[2 * kk + 1][1]);
            ph[3] = pack_h2(accS[2 * kk + 1][2], accS[2 * kk + 1][3]);
#pragma unroll
            for (int dp = 0; dp < 2; dp++) {
                const int dg0 = dp * 2, dg1 = dp * 2 + 1;
                uint32_t va[4], vb[4];
                uint32_t offa = (uint32_t)((kk * 16 + lr) * ALDK + dg0 * 16 + lc) * 2;
                uint32_t offb = (uint32_t)((kk * 16 + lr) * ALDK + dg1 * 16 + lc) * 2;
                LDSM_X4_T(va[0], va[1], va[2], va[3], Vh + offa);
                LDSM_X4_T(vb[0], vb[1], vb[2], vb[3], Vh + offb);
                MMAH(accO[2 * dg0],     ph, va[0], va[1]);
                MMAH(accO[2 * dg0 + 1], ph, va[2], va[3]);
                MMAH(accO[2 * dg1],     ph, vb[0], vb[1]);
                MMAH(accO[2 * dg1 + 1], ph, vb[2], vb[3]);
            }
        }
        __syncthreads();
    }

    // ---- epilogue: normalize, fp16 into [B][N][C] ----
    const int b = bh >> 4;
    const int h = bh & 15;
    const float inv0 = 1.0f / lrow[0];
    const float inv1 = 1.0f / lrow[1];
    const int row0 = r0t + wid * 16 + (lane >> 2);
#pragma unroll
    for (int t = 0; t < 8; t++) {
        int col = h * 64 + t * 8 + (lane & 3) * 2;
        *(uint32_t*)(g_ah + ((size_t)b * N_ + row0) * C_ + col) =
            pack_h2(accO[t][0] * inv0, accO[t][1] * inv0);
        *(uint32_t*)(g_ah + ((size_t)b * N_ + row0 + 8) * C_ + col) =
            pack_h2(accO[t][2] * inv1, accO[t][3] * inv1);
    }
}

// ---------------------------------------------------------------------------
extern "C" void kernel_launch(void* const* d_in, const int* in_sizes, int n_in,
                              void* d_out, int out_size)
{
    const float* x      = (const float*)d_in[0];
    const float* w_qkv  = (const float*)d_in[1];
    const float* b_qkv  = (const float*)d_in[2];
    const float* w_proj = (const float*)d_in[3];
    const float* b_proj = (const float*)d_in[4];
    float* out = (float*)d_out;

    cudaFuncSetAttribute(mma_gemm_kernel<0>,
                         cudaFuncAttributeMaxDynamicSharedMemorySize, SMEM_GEMM);
    cudaFuncSetAttribute(mma_gemm_kernel<1>,
                         cudaFuncAttributeMaxDynamicSharedMemorySize, SMEM_GEMM);
    cudaFuncSetAttribute(attn_mma_kernel,
                         cudaFuncAttributeMaxDynamicSharedMemorySize, SMEM_ATTN);

    // 1. fp16 conversions
    {
        int n4 = B_ * N_ * C_ / 4;
        split_kernel<<<(n4 + 255) / 256, 256>>>(x, n4);
        dim3 g1(3 * C_ / 32, C_ / 32);
        splitT_kernel<0><<<g1, 256>>>(w_qkv, 3 * C_);
        dim3 g2(C_ / 32, C_ / 32);
        splitT_kernel<1><<<g2, 256>>>(w_proj, C_);
    }

    // 2. QKV GEMM -> fp16 q(scaled) / k / v
    {
        dim3 grid(3 * C_ / 64, (B_ * N_) / 128);   // (48, 64)
        mma_gemm_kernel<0><<<grid, 128, SMEM_GEMM>>>(b_qkv, nullptr);
    }

    // 3. MMA flash attention -> g_ah
    {
        dim3 grid(B_ * H_, N_ / 64);               // (64, 32)
        attn_mma_kernel<<<grid, 128, SMEM_ATTN>>>();
    }

    // 4. Projection GEMM -> out
    {
        dim3 grid(C_ / 64, (B_ * N_) / 128);       // (16, 64)
        mma_gemm_kernel<1><<<grid, 128, SMEM_GEMM>>>(b_proj, out);
    }
}